// round 2
// baseline (speedup 1.0000x reference)
#include <cuda_runtime.h>

// Problem constants
#define Bx  2
#define Sx  2048
#define Dx  1024
#define Hx  16
#define DKx 64
#define Mx  (Bx*Sx)            // 4096 rows

// Scratch (device globals: allocation-free per harness rules)
__device__ float g_q2[(size_t)Bx*Hx*Sx*DKx];   // [b,h,s,k] projected q
__device__ float g_k2[(size_t)Bx*Hx*Sx*DKx];   // [b,h,s,k] projected k
__device__ float g_v2[(size_t)Bx*Hx*Sx*DKx];   // [b,h,s,k] projected v
__device__ float g_ao[(size_t)Bx*Sx*Hx*DKx];   // [b,s,h,k] attention output (concat layout)

// ---------------------------------------------------------------------------
// GEMM: C = A[M,K] @ W[N,K]^T + bias[N]
//   which = 0/1/2 : write to g_q2/g_k2/g_v2 in [b,h,s,k] layout
//   which = 3     : write plain row-major [M,N] to Cext
//   asrc  = 1     : read A from g_ao instead of Aext
// Tiles: 128x128x16, 256 threads, 8x8 register tile per thread.
// ---------------------------------------------------------------------------
__global__ void __launch_bounds__(256) gemm_kernel(
    const float* __restrict__ Aext, const float* __restrict__ W,
    const float* __restrict__ bias, float* __restrict__ Cext,
    int which, int asrc, int N, int K)
{
    const float* A = asrc ? g_ao : Aext;
    __shared__ float As[16][132];   // transposed A tile [k][m], pad for banks
    __shared__ float Bs[16][132];   // transposed W tile [k][n]

    int tid  = threadIdx.x;
    int tx   = tid & 15;            // 0..15 (cols)
    int ty   = tid >> 4;            // 0..15 (rows)
    int brow = blockIdx.y * 128;
    int bcol = blockIdx.x * 128;
    int lrow = tid >> 2;            // 0..63
    int lc4  = (tid & 3) * 4;       // 0,4,8,12

    float acc[8][8] = {};

    for (int k0 = 0; k0 < K; k0 += 16) {
        #pragma unroll
        for (int r = 0; r < 2; r++) {
            int row = lrow + r * 64;
            float4 va = *(const float4*)&A[(size_t)(brow + row) * K + k0 + lc4];
            As[lc4+0][row] = va.x; As[lc4+1][row] = va.y;
            As[lc4+2][row] = va.z; As[lc4+3][row] = va.w;
            float4 vb = *(const float4*)&W[(size_t)(bcol + row) * K + k0 + lc4];
            Bs[lc4+0][row] = vb.x; Bs[lc4+1][row] = vb.y;
            Bs[lc4+2][row] = vb.z; Bs[lc4+3][row] = vb.w;
        }
        __syncthreads();
        #pragma unroll
        for (int kk = 0; kk < 16; kk++) {
            float a[8], b[8];
            #pragma unroll
            for (int i = 0; i < 8; i++) a[i] = As[kk][ty*8 + i];
            #pragma unroll
            for (int j = 0; j < 8; j++) b[j] = Bs[kk][tx*8 + j];
            #pragma unroll
            for (int i = 0; i < 8; i++)
                #pragma unroll
                for (int j = 0; j < 8; j++)
                    acc[i][j] += a[i] * b[j];
        }
        __syncthreads();
    }

    float* Cp = (which == 0) ? g_q2 : (which == 1) ? g_k2 : (which == 2) ? g_v2 : Cext;
    #pragma unroll
    for (int i = 0; i < 8; i++) {
        int row = brow + ty*8 + i;
        #pragma unroll
        for (int j = 0; j < 8; j++) {
            int col = bcol + tx*8 + j;
            float v = acc[i][j] + bias[col];
            if (which == 3) {
                Cp[(size_t)row * N + col] = v;
            } else {
                int b = row >> 11, s = row & 2047;     // row = b*S + s
                int h = col >> 6,  kk = col & 63;      // col = h*DK + kk
                Cp[(((size_t)(b*Hx + h)) * Sx + s) * DKx + kk] = v;
            }
        }
    }
}

// ---------------------------------------------------------------------------
// Flash attention with role swap per reference:
//   scores = v2 @ k2^T / sqrt(DK);  attn = softmax;  out = attn @ q2
// So: Q-role = v2, K-role = k2, V-role = q2.
// Per CTA: one (b,h), Br=64 query rows; stream key blocks Bc=32.
// 256 threads as 16x16; each thread: 4x2 of S tile, 4x4 of O tile.
// Output written directly in [b,s,h,k] (concat) layout to g_ao.
// ---------------------------------------------------------------------------
__global__ void __launch_bounds__(256) flash_kernel()
{
    int bh   = blockIdx.y;          // b*H + h (0..31)
    int b    = bh >> 4;
    int h    = bh & 15;
    int row0 = blockIdx.x * 64;

    const float* Qg = g_v2 + (size_t)bh * Sx * DKx;
    const float* Kg = g_k2 + (size_t)bh * Sx * DKx;
    const float* Vg = g_q2 + (size_t)bh * Sx * DKx;

    __shared__ float Qs[64][68];    // pitch 68 floats = 17 float4 (odd -> conflict-free)
    __shared__ float Ks[32][68];
    __shared__ float Vs[32][68];
    __shared__ float Ss[64][36];    // 32 cols + pad
    __shared__ float ml[64], ll[64], al_s[64];

    int tid  = threadIdx.x;
    int tx   = tid & 15;
    int ty   = tid >> 4;
    int warp = tid >> 5;
    int lane = tid & 31;

    // Load Q block (64x64), 16 floats per thread
    {
        int row = tid >> 2, cbase = (tid & 3) * 16;
        #pragma unroll
        for (int j = 0; j < 4; j++)
            *(float4*)&Qs[row][cbase + j*4] =
                *(const float4*)&Qg[(size_t)(row0 + row) * DKx + cbase + j*4];
    }
    if (tid < 64) { ml[tid] = -1e30f; ll[tid] = 0.0f; }

    float acc[4][4] = {};

    for (int c0 = 0; c0 < Sx; c0 += 32) {
        // Load K,V blocks (32x64 each), 8 floats per thread per matrix
        {
            int row = tid >> 3, c = (tid & 7) * 8;
            const float* kp = &Kg[(size_t)(c0 + row) * DKx + c];
            const float* vp = &Vg[(size_t)(c0 + row) * DKx + c];
            *(float4*)&Ks[row][c]     = *(const float4*)kp;
            *(float4*)&Ks[row][c + 4] = *(const float4*)(kp + 4);
            *(float4*)&Vs[row][c]     = *(const float4*)vp;
            *(float4*)&Vs[row][c + 4] = *(const float4*)(vp + 4);
        }
        __syncthreads();

        // S = Q K^T * 0.125  (each thread: rows ty*4..+3, cols tx*2..+1)
        float sacc[4][2] = {};
        #pragma unroll
        for (int k = 0; k < DKx; k += 4) {
            float4 qv[4], kv[2];
            #pragma unroll
            for (int i = 0; i < 4; i++) qv[i] = *(const float4*)&Qs[ty*4 + i][k];
            #pragma unroll
            for (int j = 0; j < 2; j++) kv[j] = *(const float4*)&Ks[tx*2 + j][k];
            #pragma unroll
            for (int i = 0; i < 4; i++)
                #pragma unroll
                for (int j = 0; j < 2; j++)
                    sacc[i][j] += qv[i].x*kv[j].x + qv[i].y*kv[j].y
                                + qv[i].z*kv[j].z + qv[i].w*kv[j].w;
        }
        #pragma unroll
        for (int i = 0; i < 4; i++)
            #pragma unroll
            for (int j = 0; j < 2; j++)
                Ss[ty*4 + i][tx*2 + j] = sacc[i][j] * 0.125f;
        __syncthreads();

        // Online softmax per row: warp w owns rows w*8..w*8+7, lane = column
        #pragma unroll
        for (int rr = 0; rr < 8; rr++) {
            int row = warp*8 + rr;
            float sv = Ss[row][lane];
            float mx = sv;
            #pragma unroll
            for (int off = 16; off > 0; off >>= 1)
                mx = fmaxf(mx, __shfl_xor_sync(0xffffffff, mx, off));
            float mprev = ml[row];
            float mnew  = fmaxf(mprev, mx);
            float p     = __expf(sv - mnew);
            float sum   = p;
            #pragma unroll
            for (int off = 16; off > 0; off >>= 1)
                sum += __shfl_xor_sync(0xffffffff, sum, off);
            Ss[row][lane] = p;
            if (lane == 0) {
                float al   = __expf(mprev - mnew);
                al_s[row]  = al;
                ml[row]    = mnew;
                ll[row]    = ll[row] * al + sum;
            }
        }
        __syncthreads();

        // O = al*O + P @ V   (each thread: rows ty*4..+3, cols tx*4..+3)
        #pragma unroll
        for (int i = 0; i < 4; i++) {
            float al = al_s[ty*4 + i];
            acc[i][0] *= al; acc[i][1] *= al; acc[i][2] *= al; acc[i][3] *= al;
        }
        #pragma unroll
        for (int c = 0; c < 32; c++) {
            float4 vv = *(const float4*)&Vs[c][tx*4];
            #pragma unroll
            for (int i = 0; i < 4; i++) {
                float p = Ss[ty*4 + i][c];
                acc[i][0] += p * vv.x;
                acc[i][1] += p * vv.y;
                acc[i][2] += p * vv.z;
                acc[i][3] += p * vv.w;
            }
        }
        __syncthreads();
    }

    // Normalize and write out in [b, s, h, k] layout
    #pragma unroll
    for (int i = 0; i < 4; i++) {
        int row = ty*4 + i;
        float inv = 1.0f / ll[row];
        float4 o = make_float4(acc[i][0]*inv, acc[i][1]*inv, acc[i][2]*inv, acc[i][3]*inv);
        size_t idx = (((size_t)(b*Sx + row0 + row)) * Hx + h) * DKx + tx*4;
        *(float4*)&g_ao[idx] = o;
    }
}

// ---------------------------------------------------------------------------
// Launch
// ---------------------------------------------------------------------------
extern "C" void kernel_launch(void* const* d_in, const int* in_sizes, int n_in,
                              void* d_out, int out_size)
{
    const float* v  = (const float*)d_in[0];
    const float* k  = (const float*)d_in[1];
    const float* q  = (const float*)d_in[2];
    const float* Wq = (const float*)d_in[3];
    const float* bq = (const float*)d_in[4];
    const float* Wk = (const float*)d_in[5];
    const float* bk = (const float*)d_in[6];
    const float* Wv = (const float*)d_in[7];
    const float* bv = (const float*)d_in[8];
    const float* Wo = (const float*)d_in[9];
    const float* bo = (const float*)d_in[10];
    float* out = (float*)d_out;

    dim3 blk(256);
    dim3 gp(Dx / 128, Mx / 128);      // (8, 32) — projections & output GEMM
    dim3 ga(Sx / 64, Bx * Hx);        // (32, 32) — flash attention

    // Projections (bias included), output in [b,h,s,k]
    gemm_kernel<<<gp, blk>>>(q, Wq, bq, nullptr, /*which=*/0, /*asrc=*/0, Dx, Dx);
    gemm_kernel<<<gp, blk>>>(k, Wk, bk, nullptr, /*which=*/1, /*asrc=*/0, Dx, Dx);
    gemm_kernel<<<gp, blk>>>(v, Wv, bv, nullptr, /*which=*/2, /*asrc=*/0, Dx, Dx);

    // Attention with role swap (scores = v2 k2^T, values = q2)
    flash_kernel<<<ga, blk>>>();

    // Output projection: out = g_ao @ Wo^T + bo
    gemm_kernel<<<gp, blk>>>(nullptr, Wo, bo, out, /*which=*/3, /*asrc=*/1, Dx, Dx);
}

// round 6
// speedup vs baseline: 2.8102x; 2.8102x over previous
#include <cuda_runtime.h>
#include <cuda_bf16.h>
#include <stdint.h>

#define Bx 2
#define Sx 2048
#define Dx 1024
#define Hx 16
#define DKx 64
#define Mx (Bx*Sx)
#define BHx (Bx*Hx)
typedef __nv_bfloat16 bf16;

// ------------------------- device scratch (static) -------------------------
// split inputs / weights
__device__ __align__(256) bf16 g_qh[(size_t)Mx*Dx],  g_ql[(size_t)Mx*Dx];
__device__ __align__(256) bf16 g_kh[(size_t)Mx*Dx],  g_kl[(size_t)Mx*Dx];
__device__ __align__(256) bf16 g_vh[(size_t)Mx*Dx],  g_vl[(size_t)Mx*Dx];
__device__ __align__(256) bf16 g_Wqh[(size_t)Dx*Dx], g_Wql[(size_t)Dx*Dx];
__device__ __align__(256) bf16 g_Wkh[(size_t)Dx*Dx], g_Wkl[(size_t)Dx*Dx];
__device__ __align__(256) bf16 g_Wvh[(size_t)Dx*Dx], g_Wvl[(size_t)Dx*Dx];
__device__ __align__(256) bf16 g_Woh[(size_t)Dx*Dx], g_Wol[(size_t)Dx*Dx];
// projected per-head [b,h,s,dk] hi/lo
__device__ __align__(256) bf16 g_q2h[(size_t)BHx*Sx*DKx], g_q2l[(size_t)BHx*Sx*DKx];
__device__ __align__(256) bf16 g_k2h[(size_t)BHx*Sx*DKx], g_k2l[(size_t)BHx*Sx*DKx];
__device__ __align__(256) bf16 g_v2h[(size_t)BHx*Sx*DKx], g_v2l[(size_t)BHx*Sx*DKx];
// attention output, concat layout [b*S+s][1024] hi/lo
__device__ __align__(256) bf16 g_aoh[(size_t)Mx*Dx], g_aol[(size_t)Mx*Dx];

// ------------------------------- helpers -----------------------------------
__device__ __forceinline__ uint32_t s2u(const void* p){
    uint32_t a;
    asm("{ .reg .u64 t; cvta.to.shared.u64 t, %1; cvt.u32.u64 %0, t; }" : "=r"(a) : "l"(p));
    return a;
}
__device__ __forceinline__ uint32_t swz(uint32_t o){ return o ^ ((o >> 3) & 0x70); }
__device__ __forceinline__ uint32_t packbf(float x, float y){
    __nv_bfloat162 t = __floats2bfloat162_rn(x, y);
    return *reinterpret_cast<uint32_t*>(&t);
}
__device__ __forceinline__ float resid(float x){
    return x - __bfloat162float(__float2bfloat16(x));
}
// fast exp2 (FMA-only, arg <= ~0, rel err ~2e-6)
__device__ __forceinline__ float exp2p(float t){
    t = fmaxf(t, -100.f);
    float r = rintf(t);
    float f = t - r;
    float p = 1.3333558e-3f;
    p = fmaf(p, f, 9.6181291e-3f);
    p = fmaf(p, f, 5.5504109e-2f);
    p = fmaf(p, f, 2.4022651e-1f);
    p = fmaf(p, f, 6.9314718e-1f);
    p = fmaf(p, f, 1.0f);
    int e = (int)r;
    return p * __int_as_float((e + 127) << 23);
}
__device__ __forceinline__ void ldsm4(uint32_t* r, uint32_t a){
    asm volatile("ldmatrix.sync.aligned.m8n8.x4.shared.b16 {%0,%1,%2,%3}, [%4];"
                 : "=r"(r[0]), "=r"(r[1]), "=r"(r[2]), "=r"(r[3]) : "r"(a));
}
__device__ __forceinline__ void ldsm4t(uint32_t* r, uint32_t a){
    asm volatile("ldmatrix.sync.aligned.m8n8.x4.trans.shared.b16 {%0,%1,%2,%3}, [%4];"
                 : "=r"(r[0]), "=r"(r[1]), "=r"(r[2]), "=r"(r[3]) : "r"(a));
}
__device__ __forceinline__ void mma16816(float* c, const uint32_t* a, const uint32_t* b){
    asm volatile("mma.sync.aligned.m16n8k16.row.col.f32.bf16.bf16.f32 "
                 "{%0,%1,%2,%3}, {%4,%5,%6,%7}, {%8,%9}, {%0,%1,%2,%3};"
                 : "+f"(c[0]), "+f"(c[1]), "+f"(c[2]), "+f"(c[3])
                 : "r"(a[0]), "r"(a[1]), "r"(a[2]), "r"(a[3]), "r"(b[0]), "r"(b[1]));
}

// ----------------------- fp32 -> (hi, lo) bf16 split ------------------------
__global__ void __launch_bounds__(256) split_kernel(const float4* __restrict__ src, int sel, int n4){
    int i = blockIdx.x * 256 + threadIdx.x;
    if (i >= n4) return;
    bf16 *H, *L;
    switch (sel){
        case 0: H = g_vh;  L = g_vl;  break;
        case 1: H = g_kh;  L = g_kl;  break;
        case 2: H = g_qh;  L = g_ql;  break;
        case 3: H = g_Wqh; L = g_Wql; break;
        case 4: H = g_Wkh; L = g_Wkl; break;
        case 5: H = g_Wvh; L = g_Wvl; break;
        default:H = g_Woh; L = g_Wol; break;
    }
    float4 v = src[i];
    bf16 h0 = __float2bfloat16(v.x), h1 = __float2bfloat16(v.y);
    bf16 h2 = __float2bfloat16(v.z), h3 = __float2bfloat16(v.w);
    __nv_bfloat162* Hp = (__nv_bfloat162*)H;
    __nv_bfloat162* Lp = (__nv_bfloat162*)L;
    __nv_bfloat162 t;
    t.x = h0; t.y = h1; Hp[i*2+0] = t;
    t.x = h2; t.y = h3; Hp[i*2+1] = t;
    t.x = __float2bfloat16(v.x - __bfloat162float(h0));
    t.y = __float2bfloat16(v.y - __bfloat162float(h1)); Lp[i*2+0] = t;
    t.x = __float2bfloat16(v.z - __bfloat162float(h2));
    t.y = __float2bfloat16(v.w - __bfloat162float(h3)); Lp[i*2+1] = t;
}

// ----- split-bf16 HMMA GEMM: C = A[4096,1024] @ W[1024,1024]^T (+bias) ------
// MODE 0: fp32 row-major to Cf.  MODE 1: split per-head [b,h,s,dk] by asel.
// CTA tile 128x128, K-chunk 32 (rows hold [hi 64B | lo 64B]).
template<int MODE>
__global__ void __launch_bounds__(256,1) gemm_hmma(int asel, int bsel,
                                                   float* __restrict__ Cf,
                                                   const float* __restrict__ bias)
{
    __shared__ __align__(1024) char sm[34816];
    const int tid = threadIdx.x, wid = tid >> 5, lane = tid & 31;
    const int row0 = blockIdx.x * 128, col0 = blockIdx.y * 128;
    const uint32_t sb = s2u(sm);
    const uint32_t TB = 16384;

    const bf16 *Ah, *Al, *Bh, *Bl;
    switch (asel){
        case 0: Ah = g_qh;  Al = g_ql;  break;
        case 1: Ah = g_kh;  Al = g_kl;  break;
        case 2: Ah = g_vh;  Al = g_vl;  break;
        default:Ah = g_aoh; Al = g_aol; break;
    }
    switch (bsel){
        case 0: Bh = g_Wqh; Bl = g_Wql; break;
        case 1: Bh = g_Wkh; Bl = g_Wkl; break;
        case 2: Bh = g_Wvh; Bl = g_Wvl; break;
        default:Bh = g_Woh; Bl = g_Wol; break;
    }
    bf16 *Ch = nullptr, *Cl = nullptr;
    if (MODE == 1){
        switch (asel){
            case 0: Ch = g_q2h; Cl = g_q2l; break;
            case 1: Ch = g_k2h; Cl = g_k2l; break;
            default:Ch = g_v2h; Cl = g_v2l; break;
        }
    }

    const int wm = wid >> 2, wn = wid & 3;
    const uint32_t la15 = lane & 15, lb7 = lane & 7;
    const uint32_t x0a = ((lane >> 4) & 1) * 16;
    const uint32_t xb  = ((lane >> 3) & 3) * 16;

    float acc[4][4][4];
    #pragma unroll
    for (int mi = 0; mi < 4; mi++)
        #pragma unroll
        for (int ni = 0; ni < 4; ni++)
            #pragma unroll
            for (int j = 0; j < 4; j++) acc[mi][ni][j] = 0.f;

    for (int k0 = 0; k0 < 1024; k0 += 32){
        #pragma unroll
        for (int it = 0; it < 4; it++){       // A: 1024 uint4
            int id = tid + it*256;
            int r = id >> 3, vv = id & 7;
            int hv = vv >> 2, ci = vv & 3;
            const bf16* src = hv ? Al : Ah;
            *(uint4*)(sm + swz((uint32_t)(r*128 + hv*64 + ci*16))) =
                *(const uint4*)(src + (size_t)(row0 + r)*1024 + k0 + ci*8);
        }
        #pragma unroll
        for (int it = 0; it < 4; it++){       // B: 1024 uint4
            int id = tid + it*256;
            int r = id >> 3, vv = id & 7;
            int hv = vv >> 2, ci = vv & 3;
            const bf16* src = hv ? Bl : Bh;
            *(uint4*)(sm + TB + swz((uint32_t)(r*128 + hv*64 + ci*16))) =
                *(const uint4*)(src + (size_t)(col0 + r)*1024 + k0 + ci*8);
        }
        __syncthreads();

        uint32_t Bfh[4][4], Bfl[4][4];
        #pragma unroll
        for (int ni = 0; ni < 4; ni++){
            uint32_t rowb = wn*32 + ni*8 + lb7;
            uint32_t mask = (rowb & 7) << 4;
            uint32_t rb = sb + TB + rowb*128;
            ldsm4(Bfh[ni], rb + (xb ^ mask));
            ldsm4(Bfl[ni], rb + ((64 + xb) ^ mask));
        }
        #pragma unroll
        for (int mi = 0; mi < 4; mi++){
            uint32_t rowa = wm*64 + mi*16 + la15;
            uint32_t maska = (rowa & 7) << 4;
            uint32_t rba = sb + rowa*128;
            #pragma unroll
            for (int ks = 0; ks < 2; ks++){
                uint32_t Ahf[4], Alf[4];
                uint32_t off = (uint32_t)ks*32 + x0a;
                ldsm4(Ahf, rba + (off ^ maska));
                ldsm4(Alf, rba + ((64 + off) ^ maska));
                #pragma unroll
                for (int ni = 0; ni < 4; ni++){
                    mma16816(acc[mi][ni], Ahf, &Bfh[ni][ks*2]);
                    mma16816(acc[mi][ni], Ahf, &Bfl[ni][ks*2]);
                    mma16816(acc[mi][ni], Alf, &Bfh[ni][ks*2]);
                }
            }
        }
        __syncthreads();
    }

    // epilogue: two 64-row passes through smem staging [64][132]
    float* smf = (float*)sm;
    #pragma unroll
    for (int hf = 0; hf < 2; hf++){
        if (wm == hf){
            #pragma unroll
            for (int mi = 0; mi < 4; mi++)
                #pragma unroll
                for (int ni = 0; ni < 4; ni++)
                    #pragma unroll
                    for (int j = 0; j < 4; j++){
                        int rr = mi*16 + (lane >> 2) + 8*(j >> 1);
                        int cc = wn*32 + ni*8 + 2*(lane & 3) + (j & 1);
                        smf[rr*132 + cc] = acc[mi][ni][j];
                    }
        }
        __syncthreads();
        if (MODE == 0){
            for (int id = tid; id < 64*32; id += 256){
                int r = id >> 5, c4 = (id & 31)*4;
                int gr = row0 + hf*64 + r, gc = col0 + c4;
                float4 o;
                o.x = smf[r*132+c4]   + bias[gc];
                o.y = smf[r*132+c4+1] + bias[gc+1];
                o.z = smf[r*132+c4+2] + bias[gc+2];
                o.w = smf[r*132+c4+3] + bias[gc+3];
                *(float4*)(Cf + (size_t)gr*1024 + gc) = o;
            }
        } else {
            for (int id = tid; id < 64*64; id += 256){
                int r = id >> 6, c2 = (id & 63)*2;
                int gr = row0 + hf*64 + r, gc = col0 + c2;
                float x = smf[r*132+c2]   + bias[gc];
                float y = smf[r*132+c2+1] + bias[gc+1];
                int b_ = gr >> 11, s_ = gr & 2047;
                int h_ = gc >> 6,  dk = gc & 63;
                size_t g = (((size_t)(b_*Hx + h_))*Sx + s_)*DKx + dk;
                __nv_bfloat162 th, tl;
                th.x = __float2bfloat16(x); th.y = __float2bfloat16(y);
                tl.x = __float2bfloat16(x - __bfloat162float(th.x));
                tl.y = __float2bfloat16(y - __bfloat162float(th.y));
                *(__nv_bfloat162*)(Ch + g) = th;
                *(__nv_bfloat162*)(Cl + g) = tl;
            }
        }
        __syncthreads();
    }
}

// ------------------- flash attention (HMMA, split-bf16) ---------------------
// Role swap per reference: scores = v2 @ k2^T / 8; out = softmax(scores) @ q2.
// Q-role = v2, K-role = k2, V-role = q2. CTA: 128 q-rows of one (b,h).
__global__ void __launch_bounds__(256,1) flash_kernel(){
    __shared__ __align__(1024) char sm[34816];
    const int tid = threadIdx.x, wid = tid >> 5, lane = tid & 31;
    const int bh = blockIdx.y, row0 = blockIdx.x * 128;
    const int b = bh >> 4, h = bh & 15;
    const uint32_t sb = s2u(sm);
    const size_t hb = (size_t)bh * Sx * DKx;
    const bf16* Qh_g = g_v2h + hb; const bf16* Ql_g = g_v2l + hb;
    const bf16* Kh_g = g_k2h + hb; const bf16* Kl_g = g_k2l + hb;
    const bf16* Vh_g = g_q2h + hb; const bf16* Vl_g = g_q2l + hb;

    const uint32_t la15 = lane & 15, lb7 = lane & 7;
    const uint32_t x0a = ((lane >> 4) & 1) * 16;
    const uint32_t xb  = ((lane >> 3) & 3) * 16;

    // ---- load Q fragments (two stages of 64 rows through smem) ----
    uint32_t qh_f[4][4], ql_f[4][4];
    #pragma unroll
    for (int st = 0; st < 2; st++){
        #pragma unroll
        for (int it = 0; it < 4; it++){
            int id = tid + it*256;            // 1024 uint4 (hi 512 | lo 512)
            int half = id >> 9, i2 = id & 511;
            int r = i2 >> 3, c = i2 & 7;
            const bf16* src = half ? Ql_g : Qh_g;
            *(uint4*)(sm + half*8192 + swz((uint32_t)(r*128 + c*16))) =
                *(const uint4*)(src + (size_t)(row0 + st*64 + r)*DKx + c*8);
        }
        __syncthreads();
        if ((wid >> 2) == st){
            uint32_t lr = (uint32_t)(wid & 3)*16 + la15;
            uint32_t mask = (lr & 7) << 4;
            uint32_t base = sb + lr*128;
            #pragma unroll
            for (int ks = 0; ks < 4; ks++){
                uint32_t off = (uint32_t)ks*32 + x0a;
                ldsm4(qh_f[ks], base +        (off ^ mask));
                ldsm4(ql_f[ks], base + 8192 + (off ^ mask));
            }
        }
        __syncthreads();
    }

    float m0 = -1e30f, m1 = -1e30f, l0 = 0.f, l1 = 0.f;
    float oacc[8][4];
    #pragma unroll
    for (int n = 0; n < 8; n++){ oacc[n][0]=0.f; oacc[n][1]=0.f; oacc[n][2]=0.f; oacc[n][3]=0.f; }
    const float cs = 0.18033688f;   // 0.125 * log2(e)

    for (int c0 = 0; c0 < Sx; c0 += 64){
        // load K hi/lo, V hi/lo: 4 bufs x 64 rows x 128B
        #pragma unroll
        for (int it = 0; it < 8; it++){
            int id = tid + it*256;
            int buf = id >> 9, i2 = id & 511;
            int r = i2 >> 3, c = i2 & 7;
            const bf16* src = (buf==0)?Kh_g:(buf==1)?Kl_g:(buf==2)?Vh_g:Vl_g;
            *(uint4*)(sm + buf*8192 + swz((uint32_t)(r*128 + c*16))) =
                *(const uint4*)(src + (size_t)(c0 + r)*DKx + c*8);
        }
        __syncthreads();

        // ---- S = Q @ K^T (3 split products) ----
        float sacc[8][4];
        #pragma unroll
        for (int n = 0; n < 8; n++){ sacc[n][0]=0.f; sacc[n][1]=0.f; sacc[n][2]=0.f; sacc[n][3]=0.f; }
        #pragma unroll
        for (int n = 0; n < 8; n++){
            uint32_t rn = (uint32_t)n*8 + lb7;
            uint32_t mask = (rn & 7) << 4;
            uint32_t rb = sb + rn*128;
            uint32_t bh0[4], bh1[4], bl0[4], bl1[4];
            ldsm4(bh0, rb +        (xb ^ mask));
            ldsm4(bh1, rb +        ((64 + xb) ^ mask));
            ldsm4(bl0, rb + 8192 + (xb ^ mask));
            ldsm4(bl1, rb + 8192 + ((64 + xb) ^ mask));
            mma16816(sacc[n], qh_f[0], bh0+0);
            mma16816(sacc[n], qh_f[1], bh0+2);
            mma16816(sacc[n], qh_f[2], bh1+0);
            mma16816(sacc[n], qh_f[3], bh1+2);
            mma16816(sacc[n], qh_f[0], bl0+0);
            mma16816(sacc[n], qh_f[1], bl0+2);
            mma16816(sacc[n], qh_f[2], bl1+0);
            mma16816(sacc[n], qh_f[3], bl1+2);
            mma16816(sacc[n], ql_f[0], bh0+0);
            mma16816(sacc[n], ql_f[1], bh0+2);
            mma16816(sacc[n], ql_f[2], bh1+0);
            mma16816(sacc[n], ql_f[3], bh1+2);
        }

        // ---- online softmax (rows r0 = lane>>2, r1 = r0+8 within warp tile) ----
        float mx0 = sacc[0][0], mx1 = sacc[0][2];
        #pragma unroll
        for (int n = 0; n < 8; n++){
            mx0 = fmaxf(mx0, fmaxf(sacc[n][0], sacc[n][1]));
            mx1 = fmaxf(mx1, fmaxf(sacc[n][2], sacc[n][3]));
        }
        mx0 = fmaxf(mx0, __shfl_xor_sync(0xffffffffu, mx0, 1));
        mx0 = fmaxf(mx0, __shfl_xor_sync(0xffffffffu, mx0, 2));
        mx1 = fmaxf(mx1, __shfl_xor_sync(0xffffffffu, mx1, 1));
        mx1 = fmaxf(mx1, __shfl_xor_sync(0xffffffffu, mx1, 2));
        float mn0 = fmaxf(m0, mx0), mn1 = fmaxf(m1, mx1);
        float al0 = exp2p((m0 - mn0)*cs), al1 = exp2p((m1 - mn1)*cs);
        m0 = mn0; m1 = mn1;
        float s0 = 0.f, s1 = 0.f;
        #pragma unroll
        for (int n = 0; n < 8; n++){
            sacc[n][0] = exp2p((sacc[n][0] - mn0)*cs); s0 += sacc[n][0];
            sacc[n][1] = exp2p((sacc[n][1] - mn0)*cs); s0 += sacc[n][1];
            sacc[n][2] = exp2p((sacc[n][2] - mn1)*cs); s1 += sacc[n][2];
            sacc[n][3] = exp2p((sacc[n][3] - mn1)*cs); s1 += sacc[n][3];
        }
        s0 += __shfl_xor_sync(0xffffffffu, s0, 1);
        s0 += __shfl_xor_sync(0xffffffffu, s0, 2);
        s1 += __shfl_xor_sync(0xffffffffu, s1, 1);
        s1 += __shfl_xor_sync(0xffffffffu, s1, 2);
        l0 = l0*al0 + s0; l1 = l1*al1 + s1;
        #pragma unroll
        for (int n = 0; n < 8; n++){
            oacc[n][0] *= al0; oacc[n][1] *= al0;
            oacc[n][2] *= al1; oacc[n][3] *= al1;
        }

        // ---- O += P @ V (P split in-register; V split in smem) ----
        #pragma unroll
        for (int kp = 0; kp < 2; kp++){
            uint32_t pah[2][4], pal[2][4];
            #pragma unroll
            for (int kk = 0; kk < 2; kk++){
                int n0 = (kp*2 + kk)*2, n1 = n0 + 1;
                pah[kk][0] = packbf(sacc[n0][0], sacc[n0][1]);
                pah[kk][1] = packbf(sacc[n0][2], sacc[n0][3]);
                pah[kk][2] = packbf(sacc[n1][0], sacc[n1][1]);
                pah[kk][3] = packbf(sacc[n1][2], sacc[n1][3]);
                pal[kk][0] = packbf(resid(sacc[n0][0]), resid(sacc[n0][1]));
                pal[kk][1] = packbf(resid(sacc[n0][2]), resid(sacc[n0][3]));
                pal[kk][2] = packbf(resid(sacc[n1][0]), resid(sacc[n1][1]));
                pal[kk][3] = packbf(resid(sacc[n1][2]), resid(sacc[n1][3]));
            }
            uint32_t vrow = (uint32_t)kp*32 + lane;
            uint32_t vmask = (vrow & 7) << 4;
            uint32_t vrb = vrow*128;
            #pragma unroll
            for (int nd = 0; nd < 8; nd++){
                uint32_t bvh[4], bvl[4];
                uint32_t off = ((uint32_t)nd*16) ^ vmask;
                ldsm4t(bvh, sb + 16384 + vrb + off);
                ldsm4t(bvl, sb + 24576 + vrb + off);
                mma16816(oacc[nd], pah[0], bvh+0);
                mma16816(oacc[nd], pah[0], bvl+0);
                mma16816(oacc[nd], pal[0], bvh+0);
                mma16816(oacc[nd], pah[1], bvh+2);
                mma16816(oacc[nd], pah[1], bvl+2);
                mma16816(oacc[nd], pal[1], bvh+2);
            }
        }
        __syncthreads();
    }

    // ---- epilogue: normalize, stage [128][68], write split concat ao ----
    float inv0 = 1.f / l0, inv1 = 1.f / l1;
    float* smf = (float*)sm;
    int r0g = wid*16 + (lane >> 2), r1g = r0g + 8;
    #pragma unroll
    for (int n = 0; n < 8; n++){
        int cb = n*8 + 2*(lane & 3);
        smf[r0g*68 + cb]   = oacc[n][0]*inv0;
        smf[r0g*68 + cb+1] = oacc[n][1]*inv0;
        smf[r1g*68 + cb]   = oacc[n][2]*inv1;
        smf[r1g*68 + cb+1] = oacc[n][3]*inv1;
    }
    __syncthreads();
    for (int id = tid; id < 128*32; id += 256){
        int r = id >> 5, c2 = (id & 31)*2;
        float x = smf[r*68 + c2], y = smf[r*68 + c2 + 1];
        size_t g = ((size_t)(b*Sx + row0 + r))*Dx + h*DKx + c2;
        __nv_bfloat162 th, tl;
        th.x = __float2bfloat16(x); th.y = __float2bfloat16(y);
        tl.x = __float2bfloat16(x - __bfloat162float(th.x));
        tl.y = __float2bfloat16(y - __bfloat162float(th.y));
        *(__nv_bfloat162*)(g_aoh + g) = th;
        *(__nv_bfloat162*)(g_aol + g) = tl;
    }
}

// --------------------------------- launch -----------------------------------
extern "C" void kernel_launch(void* const* d_in, const int* in_sizes, int n_in,
                              void* d_out, int out_size)
{
    const float* v  = (const float*)d_in[0];
    const float* k  = (const float*)d_in[1];
    const float* q  = (const float*)d_in[2];
    const float* bq = (const float*)d_in[4];
    const float* bk = (const float*)d_in[6];
    const float* bv = (const float*)d_in[8];
    const float* bo = (const float*)d_in[10];
    const float* Wq = (const float*)d_in[3];
    const float* Wk = (const float*)d_in[5];
    const float* Wv = (const float*)d_in[7];
    const float* Wo = (const float*)d_in[9];
    (void)Wq; (void)Wk; (void)Wv; (void)Wo;
    float* out = (float*)d_out;

    const int n4in = Mx*Dx/4, n4w = Dx*Dx/4;
    split_kernel<<<n4in/256, 256>>>((const float4*)v, 0, n4in);
    split_kernel<<<n4in/256, 256>>>((const float4*)k, 1, n4in);
    split_kernel<<<n4in/256, 256>>>((const float4*)q, 2, n4in);
    split_kernel<<<n4w/256, 256>>>((const float4*)d_in[3], 3, n4w);
    split_kernel<<<n4w/256, 256>>>((const float4*)d_in[5], 4, n4w);
    split_kernel<<<n4w/256, 256>>>((const float4*)d_in[7], 5, n4w);
    split_kernel<<<n4w/256, 256>>>((const float4*)d_in[9], 6, n4w);

    dim3 gg(Mx/128, Dx/128);   // (32, 8)
    // projections -> per-head split layouts
    gemm_hmma<1><<<gg, 256>>>(0, 0, nullptr, bq);   // q @ Wq^T -> q2 (V-role)
    gemm_hmma<1><<<gg, 256>>>(1, 1, nullptr, bk);   // k @ Wk^T -> k2 (K-role)
    gemm_hmma<1><<<gg, 256>>>(2, 2, nullptr, bv);   // v @ Wv^T -> v2 (Q-role)

    // fused attention with role swap -> ao (concat, split)
    flash_kernel<<<dim3(Sx/128, BHx), 256>>>();

    // out = ao @ Wo^T + bo
    gemm_hmma<0><<<gg, 256>>>(3, 3, out, bo);
}

// round 10
// speedup vs baseline: 3.6879x; 1.3123x over previous
#include <cuda_runtime.h>
#include <cuda_bf16.h>
#include <stdint.h>

#define Bx 2
#define Sx 2048
#define Dx 1024
#define Hx 16
#define DKx 64
#define Mx (Bx*Sx)
#define BHx (Bx*Hx)
typedef __nv_bfloat16 bf16;

// ------------------------- device scratch (static) -------------------------
__device__ __align__(256) bf16 g_qh[(size_t)Mx*Dx],  g_ql[(size_t)Mx*Dx];
__device__ __align__(256) bf16 g_kh[(size_t)Mx*Dx],  g_kl[(size_t)Mx*Dx];
__device__ __align__(256) bf16 g_vh[(size_t)Mx*Dx],  g_vl[(size_t)Mx*Dx];
__device__ __align__(256) bf16 g_Wqh[(size_t)Dx*Dx], g_Wql[(size_t)Dx*Dx];
__device__ __align__(256) bf16 g_Wkh[(size_t)Dx*Dx], g_Wkl[(size_t)Dx*Dx];
__device__ __align__(256) bf16 g_Wvh[(size_t)Dx*Dx], g_Wvl[(size_t)Dx*Dx];
__device__ __align__(256) bf16 g_Woh[(size_t)Dx*Dx], g_Wol[(size_t)Dx*Dx];
__device__ __align__(256) bf16 g_q2h[(size_t)BHx*Sx*DKx], g_q2l[(size_t)BHx*Sx*DKx];
__device__ __align__(256) bf16 g_k2h[(size_t)BHx*Sx*DKx], g_k2l[(size_t)BHx*Sx*DKx];
__device__ __align__(256) bf16 g_v2h[(size_t)BHx*Sx*DKx], g_v2l[(size_t)BHx*Sx*DKx];
__device__ __align__(256) bf16 g_aoh[(size_t)Mx*Dx], g_aol[(size_t)Mx*Dx];

// ------------------------------- helpers -----------------------------------
__device__ __forceinline__ uint32_t s2u(const void* p){
    uint32_t a;
    asm("{ .reg .u64 t; cvta.to.shared.u64 t, %1; cvt.u32.u64 %0, t; }" : "=r"(a) : "l"(p));
    return a;
}
__device__ __forceinline__ uint32_t swz(uint32_t o){ return o ^ ((o >> 3) & 0x70); }
__device__ __forceinline__ uint32_t packbf(float x, float y){
    __nv_bfloat162 t = __floats2bfloat162_rn(x, y);
    return *reinterpret_cast<uint32_t*>(&t);
}
__device__ __forceinline__ float resid(float x){
    return x - __bfloat162float(__float2bfloat16(x));
}
__device__ __forceinline__ float exp2p(float t){
    t = fmaxf(t, -100.f);
    float r = rintf(t);
    float f = t - r;
    float p = 1.3333558e-3f;
    p = fmaf(p, f, 9.6181291e-3f);
    p = fmaf(p, f, 5.5504109e-2f);
    p = fmaf(p, f, 2.4022651e-1f);
    p = fmaf(p, f, 6.9314718e-1f);
    p = fmaf(p, f, 1.0f);
    int e = (int)r;
    return p * __int_as_float((e + 127) << 23);
}
__device__ __forceinline__ void ldsm4(uint32_t* r, uint32_t a){
    asm volatile("ldmatrix.sync.aligned.m8n8.x4.shared.b16 {%0,%1,%2,%3}, [%4];"
                 : "=r"(r[0]), "=r"(r[1]), "=r"(r[2]), "=r"(r[3]) : "r"(a));
}
__device__ __forceinline__ void ldsm4t(uint32_t* r, uint32_t a){
    asm volatile("ldmatrix.sync.aligned.m8n8.x4.trans.shared.b16 {%0,%1,%2,%3}, [%4];"
                 : "=r"(r[0]), "=r"(r[1]), "=r"(r[2]), "=r"(r[3]) : "r"(a));
}
__device__ __forceinline__ void mma16816(float* c, const uint32_t* a, const uint32_t* b){
    asm volatile("mma.sync.aligned.m16n8k16.row.col.f32.bf16.bf16.f32 "
                 "{%0,%1,%2,%3}, {%4,%5,%6,%7}, {%8,%9}, {%0,%1,%2,%3};"
                 : "+f"(c[0]), "+f"(c[1]), "+f"(c[2]), "+f"(c[3])
                 : "r"(a[0]), "r"(a[1]), "r"(a[2]), "r"(a[3]), "r"(b[0]), "r"(b[1]));
}
__device__ __forceinline__ void cpa(uint32_t dst, const void* src){
    asm volatile("cp.async.cg.shared.global [%0], [%1], 16;" :: "r"(dst), "l"(src));
}
#define CP_COMMIT() asm volatile("cp.async.commit_group;" ::: "memory")
#define CP_WAIT1()  asm volatile("cp.async.wait_group 1;" ::: "memory")
#define CP_WAIT0()  asm volatile("cp.async.wait_group 0;" ::: "memory")

// ----------------------- fp32 -> (hi, lo) bf16 split (all tensors) ----------
__global__ void __launch_bounds__(256) split_all(
    const float4* __restrict__ v, const float4* __restrict__ k, const float4* __restrict__ q,
    const float4* __restrict__ wq, const float4* __restrict__ wk,
    const float4* __restrict__ wv, const float4* __restrict__ wo)
{
    int sel = blockIdx.y;
    int i = blockIdx.x * 256 + threadIdx.x;
    const float4* src; bf16 *H, *L; int n4;
    switch (sel){
        case 0: src=v;  H=g_vh;  L=g_vl;  n4=Mx*Dx/4; break;
        case 1: src=k;  H=g_kh;  L=g_kl;  n4=Mx*Dx/4; break;
        case 2: src=q;  H=g_qh;  L=g_ql;  n4=Mx*Dx/4; break;
        case 3: src=wq; H=g_Wqh; L=g_Wql; n4=Dx*Dx/4; break;
        case 4: src=wk; H=g_Wkh; L=g_Wkl; n4=Dx*Dx/4; break;
        case 5: src=wv; H=g_Wvh; L=g_Wvl; n4=Dx*Dx/4; break;
        default:src=wo; H=g_Woh; L=g_Wol; n4=Dx*Dx/4; break;
    }
    if (i >= n4) return;
    float4 x = src[i];
    bf16 h0 = __float2bfloat16(x.x), h1 = __float2bfloat16(x.y);
    bf16 h2 = __float2bfloat16(x.z), h3 = __float2bfloat16(x.w);
    __nv_bfloat162* Hp = (__nv_bfloat162*)H;
    __nv_bfloat162* Lp = (__nv_bfloat162*)L;
    __nv_bfloat162 t;
    t.x = h0; t.y = h1; Hp[i*2+0] = t;
    t.x = h2; t.y = h3; Hp[i*2+1] = t;
    t.x = __float2bfloat16(x.x - __bfloat162float(h0));
    t.y = __float2bfloat16(x.y - __bfloat162float(h1)); Lp[i*2+0] = t;
    t.x = __float2bfloat16(x.z - __bfloat162float(h2));
    t.y = __float2bfloat16(x.w - __bfloat162float(h3)); Lp[i*2+1] = t;
}

// ----- split-bf16 HMMA GEMM: C = A[4096,1024] @ W[1024,1024]^T (+bias) ------
// CTA tile 128x64, K-chunk 32, cp.async 2-stage pipeline. 8 warps (4x2).
// MODE 0: fp32 row-major to Cf.  MODE 1: split per-head [b,h,s,dk].
template<int MODE>
__global__ void __launch_bounds__(256,2) gemm_hmma(int asel, int bsel,
                                                   float* __restrict__ Cf,
                                                   const float* __restrict__ bias)
{
    __shared__ __align__(1024) char sm[49152];   // 2 stages x (A 16K + B 8K)
    const int tid = threadIdx.x, wid = tid >> 5, lane = tid & 31;
    const int row0 = blockIdx.x * 128, col0 = blockIdx.y * 64;
    const uint32_t sb = s2u(sm);

    const bf16 *Ah, *Al, *Bh, *Bl;
    switch (asel){
        case 0: Ah = g_qh;  Al = g_ql;  break;
        case 1: Ah = g_kh;  Al = g_kl;  break;
        case 2: Ah = g_vh;  Al = g_vl;  break;
        default:Ah = g_aoh; Al = g_aol; break;
    }
    switch (bsel){
        case 0: Bh = g_Wqh; Bl = g_Wql; break;
        case 1: Bh = g_Wkh; Bl = g_Wkl; break;
        case 2: Bh = g_Wvh; Bl = g_Wvl; break;
        default:Bh = g_Woh; Bl = g_Wol; break;
    }
    bf16 *Ch = nullptr, *Cl = nullptr;
    if (MODE == 1){
        switch (asel){
            case 0: Ch = g_q2h; Cl = g_q2l; break;
            case 1: Ch = g_k2h; Cl = g_k2l; break;
            default:Ch = g_v2h; Cl = g_v2l; break;
        }
    }

    const int wm = wid >> 1, wn = wid & 1;          // warp tile 32x32
    const uint32_t la15 = lane & 15, lb7 = lane & 7;
    const uint32_t x0a = ((lane >> 4) & 1) * 16;
    const uint32_t xb  = ((lane >> 3) & 3) * 16;

    float acc[2][4][4];
    #pragma unroll
    for (int mi = 0; mi < 2; mi++)
        #pragma unroll
        for (int ni = 0; ni < 4; ni++)
            #pragma unroll
            for (int j = 0; j < 4; j++) acc[mi][ni][j] = 0.f;

    auto load_stage = [&](int st, int kc){
        const int k0 = kc * 32;
        const uint32_t base = sb + (uint32_t)st * 24576;
        #pragma unroll
        for (int it = 0; it < 4; it++){             // A: 1024 lines
            int id = tid + it*256;
            int r = id >> 3, vv = id & 7, hv = vv >> 2, ci = vv & 3;
            const bf16* src = hv ? Al : Ah;
            cpa(base + swz((uint32_t)(r*128 + hv*64 + ci*16)),
                src + (size_t)(row0 + r)*1024 + k0 + ci*8);
        }
        #pragma unroll
        for (int it = 0; it < 2; it++){             // B: 512 lines
            int id = tid + it*256;
            int r = id >> 3, vv = id & 7, hv = vv >> 2, ci = vv & 3;
            const bf16* src = hv ? Bl : Bh;
            cpa(base + 16384 + swz((uint32_t)(r*128 + hv*64 + ci*16)),
                src + (size_t)(col0 + r)*1024 + k0 + ci*8);
        }
    };

    load_stage(0, 0); CP_COMMIT();
    for (int ci = 0; ci < 32; ci++){
        if (ci + 1 < 32) load_stage((ci+1) & 1, ci+1);
        CP_COMMIT();
        CP_WAIT1();
        __syncthreads();
        const uint32_t ta = sb + (uint32_t)(ci & 1) * 24576;
        const uint32_t tb = ta + 16384;

        uint32_t Bfh[4][4], Bfl[4][4];
        #pragma unroll
        for (int ni = 0; ni < 4; ni++){
            uint32_t rowb = wn*32 + ni*8 + lb7;
            uint32_t mask = (rowb & 7) << 4;
            uint32_t rb = tb + rowb*128;
            ldsm4(Bfh[ni], rb + (xb ^ mask));
            ldsm4(Bfl[ni], rb + ((64 + xb) ^ mask));
        }
        #pragma unroll
        for (int mi = 0; mi < 2; mi++){
            uint32_t rowa = wm*32 + mi*16 + la15;
            uint32_t maska = (rowa & 7) << 4;
            uint32_t rba = ta + rowa*128;
            #pragma unroll
            for (int ks = 0; ks < 2; ks++){
                uint32_t Ahf[4], Alf[4];
                uint32_t off = (uint32_t)ks*32 + x0a;
                ldsm4(Ahf, rba + (off ^ maska));
                ldsm4(Alf, rba + ((64 + off) ^ maska));
                #pragma unroll
                for (int ni = 0; ni < 4; ni++){
                    mma16816(acc[mi][ni], Ahf, &Bfh[ni][ks*2]);
                    mma16816(acc[mi][ni], Ahf, &Bfl[ni][ks*2]);
                    mma16816(acc[mi][ni], Alf, &Bfh[ni][ks*2]);
                }
            }
        }
        __syncthreads();
    }
    CP_WAIT0();
    __syncthreads();

    // epilogue: stage full 128x64 tile [128][68] in smem, coalesced stores
    float* smf = (float*)sm;
    #pragma unroll
    for (int mi = 0; mi < 2; mi++)
        #pragma unroll
        for (int ni = 0; ni < 4; ni++)
            #pragma unroll
            for (int j = 0; j < 4; j++){
                int rr = wm*32 + mi*16 + (lane >> 2) + 8*(j >> 1);
                int cc = wn*32 + ni*8 + 2*(lane & 3) + (j & 1);
                smf[rr*68 + cc] = acc[mi][ni][j];
            }
    __syncthreads();
    if (MODE == 0){
        #pragma unroll
        for (int it = 0; it < 8; it++){
            int id = tid + it*256;                   // 2048 float4s
            int r = id >> 4, c4 = (id & 15)*4;
            int gr = row0 + r, gc = col0 + c4;
            float4 o;
            o.x = smf[r*68+c4]   + bias[gc];
            o.y = smf[r*68+c4+1] + bias[gc+1];
            o.z = smf[r*68+c4+2] + bias[gc+2];
            o.w = smf[r*68+c4+3] + bias[gc+3];
            *(float4*)(Cf + (size_t)gr*1024 + gc) = o;
        }
    } else {
        #pragma unroll
        for (int it = 0; it < 16; it++){
            int id = tid + it*256;                   // 4096 bf16x2 pairs
            int r = id >> 5, c2 = (id & 31)*2;
            int gr = row0 + r, gc = col0 + c2;
            float x = smf[r*68+c2]   + bias[gc];
            float y = smf[r*68+c2+1] + bias[gc+1];
            int b_ = gr >> 11, s_ = gr & 2047;
            int h_ = gc >> 6,  dk = gc & 63;
            size_t g = (((size_t)(b_*Hx + h_))*Sx + s_)*DKx + dk;
            __nv_bfloat162 th, tl;
            th.x = __float2bfloat16(x); th.y = __float2bfloat16(y);
            tl.x = __float2bfloat16(x - __bfloat162float(th.x));
            tl.y = __float2bfloat16(y - __bfloat162float(th.y));
            *(__nv_bfloat162*)(Ch + g) = th;
            *(__nv_bfloat162*)(Cl + g) = tl;
        }
    }
}

// ------------------- flash attention (HMMA, split-bf16) ---------------------
// Role swap: scores = v2 @ k2^T / 8; out = softmax @ q2.
// CTA: 128 q-rows of one (b,h); KV chunks of 32, cp.async 2-stage.
// Warp w owns q-rows w*16..w*16+15.
__global__ void __launch_bounds__(256,2) flash_kernel(){
    __shared__ __align__(1024) char sm[32768];   // 2 stages x 16KB (Kh|Kl|Vh|Vl)
    const int tid = threadIdx.x, wid = tid >> 5, lane = tid & 31;
    const int bh = blockIdx.y, row0 = blockIdx.x * 128;
    const int b = bh >> 4, h = bh & 15;
    const uint32_t sb = s2u(sm);
    const size_t hb = (size_t)bh * Sx * DKx;
    const bf16* Qh_g = g_v2h + hb; const bf16* Ql_g = g_v2l + hb;
    const bf16* Kh_g = g_k2h + hb; const bf16* Kl_g = g_k2l + hb;
    const bf16* Vh_g = g_q2h + hb; const bf16* Vl_g = g_q2l + hb;

    const uint32_t la15 = lane & 15, lb7 = lane & 7;
    const uint32_t x0a = ((lane >> 4) & 1) * 16;
    const uint32_t xb  = ((lane >> 3) & 3) * 16;

    // ---- Q load (32KB) + fragment extraction ----
    #pragma unroll
    for (int it = 0; it < 8; it++){
        int id = tid + it*256;                     // 2048 lines
        int half = id >> 10, i2 = id & 1023;
        int r = i2 >> 3, c = i2 & 7;
        const bf16* src = half ? Ql_g : Qh_g;
        cpa(sb + (uint32_t)half*16384 + swz((uint32_t)(r*128 + c*16)),
            src + (size_t)(row0 + r)*DKx + c*8);
    }
    CP_COMMIT(); CP_WAIT0();
    __syncthreads();
    uint32_t qh_f[4][4], ql_f[4][4];
    {
        uint32_t lr = (uint32_t)wid*16 + la15;
        uint32_t qmask = (lr & 7) << 4;
        uint32_t qb = sb + lr*128;
        #pragma unroll
        for (int ks = 0; ks < 4; ks++){
            uint32_t off = (uint32_t)ks*32 + x0a;
            ldsm4(qh_f[ks], qb +         (off ^ qmask));
            ldsm4(ql_f[ks], qb + 16384 + (off ^ qmask));
        }
    }
    __syncthreads();

    float m0 = -1e30f, m1 = -1e30f, l0 = 0.f, l1 = 0.f;
    float oacc[8][4];
    #pragma unroll
    for (int n = 0; n < 8; n++){ oacc[n][0]=0.f; oacc[n][1]=0.f; oacc[n][2]=0.f; oacc[n][3]=0.f; }
    const float cs = 0.18033688f;   // 0.125 * log2(e)

    auto load_kv = [&](int st, int kc){
        const int r0k = kc * 32;
        const uint32_t base = sb + (uint32_t)st * 16384;
        #pragma unroll
        for (int it = 0; it < 4; it++){
            int id = tid + it*256;                 // 1024 lines, 4 bufs x 256
            int buf = id >> 8, i2 = id & 255;
            int r = i2 >> 3, c = i2 & 7;
            const bf16* src = (buf==0)?Kh_g:(buf==1)?Kl_g:(buf==2)?Vh_g:Vl_g;
            cpa(base + (uint32_t)buf*4096 + swz((uint32_t)(r*128 + c*16)),
                src + (size_t)(r0k + r)*DKx + c*8);
        }
    };

    load_kv(0, 0); CP_COMMIT();
    for (int ci = 0; ci < 64; ci++){
        if (ci + 1 < 64) load_kv((ci+1) & 1, ci+1);
        CP_COMMIT();
        CP_WAIT1();
        __syncthreads();
        const uint32_t st = sb + (uint32_t)(ci & 1) * 16384;

        // ---- S = Q @ K^T (3 split products), 32 key rows ----
        float sacc[4][4];
        #pragma unroll
        for (int n = 0; n < 4; n++){ sacc[n][0]=0.f; sacc[n][1]=0.f; sacc[n][2]=0.f; sacc[n][3]=0.f; }
        #pragma unroll
        for (int n = 0; n < 4; n++){
            uint32_t rn = (uint32_t)n*8 + lb7;
            uint32_t mask = (rn & 7) << 4;
            uint32_t rb = st + rn*128;
            uint32_t bh0[4], bh1[4], bl0[4], bl1[4];
            ldsm4(bh0, rb +        (xb ^ mask));
            ldsm4(bh1, rb +        ((64 + xb) ^ mask));
            ldsm4(bl0, rb + 4096 + (xb ^ mask));
            ldsm4(bl1, rb + 4096 + ((64 + xb) ^ mask));
            mma16816(sacc[n], qh_f[0], bh0+0);
            mma16816(sacc[n], qh_f[1], bh0+2);
            mma16816(sacc[n], qh_f[2], bh1+0);
            mma16816(sacc[n], qh_f[3], bh1+2);
            mma16816(sacc[n], qh_f[0], bl0+0);
            mma16816(sacc[n], qh_f[1], bl0+2);
            mma16816(sacc[n], qh_f[2], bl1+0);
            mma16816(sacc[n], qh_f[3], bl1+2);
            mma16816(sacc[n], ql_f[0], bh0+0);
            mma16816(sacc[n], ql_f[1], bh0+2);
            mma16816(sacc[n], ql_f[2], bh1+0);
            mma16816(sacc[n], ql_f[3], bh1+2);
        }

        // ---- online softmax ----
        float mx0 = sacc[0][0], mx1 = sacc[0][2];
        #pragma unroll
        for (int n = 0; n < 4; n++){
            mx0 = fmaxf(mx0, fmaxf(sacc[n][0], sacc[n][1]));
            mx1 = fmaxf(mx1, fmaxf(sacc[n][2], sacc[n][3]));
        }
        mx0 = fmaxf(mx0, __shfl_xor_sync(0xffffffffu, mx0, 1));
        mx0 = fmaxf(mx0, __shfl_xor_sync(0xffffffffu, mx0, 2));
        mx1 = fmaxf(mx1, __shfl_xor_sync(0xffffffffu, mx1, 1));
        mx1 = fmaxf(mx1, __shfl_xor_sync(0xffffffffu, mx1, 2));
        float mn0 = fmaxf(m0, mx0), mn1 = fmaxf(m1, mx1);
        float al0 = exp2p((m0 - mn0)*cs), al1 = exp2p((m1 - mn1)*cs);
        m0 = mn0; m1 = mn1;
        float s0 = 0.f, s1 = 0.f;
        #pragma unroll
        for (int n = 0; n < 4; n++){
            sacc[n][0] = exp2p((sacc[n][0] - mn0)*cs); s0 += sacc[n][0];
            sacc[n][1] = exp2p((sacc[n][1] - mn0)*cs); s0 += sacc[n][1];
            sacc[n][2] = exp2p((sacc[n][2] - mn1)*cs); s1 += sacc[n][2];
            sacc[n][3] = exp2p((sacc[n][3] - mn1)*cs); s1 += sacc[n][3];
        }
        s0 += __shfl_xor_sync(0xffffffffu, s0, 1);
        s0 += __shfl_xor_sync(0xffffffffu, s0, 2);
        s1 += __shfl_xor_sync(0xffffffffu, s1, 1);
        s1 += __shfl_xor_sync(0xffffffffu, s1, 2);
        l0 = l0*al0 + s0; l1 = l1*al1 + s1;
        #pragma unroll
        for (int n = 0; n < 8; n++){
            oacc[n][0] *= al0; oacc[n][1] *= al0;
            oacc[n][2] *= al1; oacc[n][3] *= al1;
        }

        // ---- O += P @ V (P split in-register; V split in smem) ----
        uint32_t pah[2][4], pal[2][4];
        #pragma unroll
        for (int kk = 0; kk < 2; kk++){
            int n0 = kk*2, n1 = kk*2 + 1;
            pah[kk][0] = packbf(sacc[n0][0], sacc[n0][1]);
            pah[kk][1] = packbf(sacc[n0][2], sacc[n0][3]);
            pah[kk][2] = packbf(sacc[n1][0], sacc[n1][1]);
            pah[kk][3] = packbf(sacc[n1][2], sacc[n1][3]);
            pal[kk][0] = packbf(resid(sacc[n0][0]), resid(sacc[n0][1]));
            pal[kk][1] = packbf(resid(sacc[n0][2]), resid(sacc[n0][3]));
            pal[kk][2] = packbf(resid(sacc[n1][0]), resid(sacc[n1][1]));
            pal[kk][3] = packbf(resid(sacc[n1][2]), resid(sacc[n1][3]));
        }
        {
            uint32_t vmask = (lane & 7) << 4;
            uint32_t vbh = st + 8192  + (uint32_t)lane*128;
            uint32_t vbl = st + 12288 + (uint32_t)lane*128;
            #pragma unroll
            for (int nd = 0; nd < 8; nd++){
                uint32_t bvh[4], bvl[4];
                uint32_t off = ((uint32_t)nd*16) ^ vmask;
                ldsm4t(bvh, vbh + off);
                ldsm4t(bvl, vbl + off);
                mma16816(oacc[nd], pah[0], bvh+0);
                mma16816(oacc[nd], pah[0], bvl+0);
                mma16816(oacc[nd], pal[0], bvh+0);
                mma16816(oacc[nd], pah[1], bvh+2);
                mma16816(oacc[nd], pah[1], bvl+2);
                mma16816(oacc[nd], pal[1], bvh+2);
            }
        }
        __syncthreads();
    }

    // ---- epilogue: normalize, stage in two 64-row passes, split writes ----
    float inv0 = 1.f / l0, inv1 = 1.f / l1;
    float* smf = (float*)sm;
    #pragma unroll
    for (int hf = 0; hf < 2; hf++){
        if ((wid >> 2) == hf){
            int r0l = (wid & 3)*16 + (lane >> 2), r1l = r0l + 8;
            #pragma unroll
            for (int nd = 0; nd < 8; nd++){
                int cb = nd*8 + 2*(lane & 3);
                smf[r0l*68 + cb]   = oacc[nd][0]*inv0;
                smf[r0l*68 + cb+1] = oacc[nd][1]*inv0;
                smf[r1l*68 + cb]   = oacc[nd][2]*inv1;
                smf[r1l*68 + cb+1] = oacc[nd][3]*inv1;
            }
        }
        __syncthreads();
        #pragma unroll
        for (int it = 0; it < 8; it++){
            int id = tid + it*256;                 // 2048 pairs
            int r = id >> 5, c2 = (id & 31)*2;
            int gr = row0 + hf*64 + r;
            float x = smf[r*68 + c2], y = smf[r*68 + c2 + 1];
            size_t g = ((size_t)(b*Sx + gr))*Dx + h*DKx + c2;
            __nv_bfloat162 th, tl;
            th.x = __float2bfloat16(x); th.y = __float2bfloat16(y);
            tl.x = __float2bfloat16(x - __bfloat162float(th.x));
            tl.y = __float2bfloat16(y - __bfloat162float(th.y));
            *(__nv_bfloat162*)(g_aoh + g) = th;
            *(__nv_bfloat162*)(g_aol + g) = tl;
        }
        __syncthreads();
    }
}

// --------------------------------- launch -----------------------------------
extern "C" void kernel_launch(void* const* d_in, const int* in_sizes, int n_in,
                              void* d_out, int out_size)
{
    const float* bq = (const float*)d_in[4];
    const float* bk = (const float*)d_in[6];
    const float* bv = (const float*)d_in[8];
    const float* bo = (const float*)d_in[10];
    float* out = (float*)d_out;

    split_all<<<dim3(Mx*Dx/4/256, 7), 256>>>(
        (const float4*)d_in[0], (const float4*)d_in[1], (const float4*)d_in[2],
        (const float4*)d_in[3], (const float4*)d_in[5], (const float4*)d_in[7],
        (const float4*)d_in[9]);

    dim3 gg(Mx/128, Dx/64);    // (32, 16)
    gemm_hmma<1><<<gg, 256>>>(0, 0, nullptr, bq);   // q @ Wq^T -> q2 (V-role)
    gemm_hmma<1><<<gg, 256>>>(1, 1, nullptr, bk);   // k @ Wk^T -> k2 (K-role)
    gemm_hmma<1><<<gg, 256>>>(2, 2, nullptr, bv);   // v @ Wv^T -> v2 (Q-role)

    flash_kernel<<<dim3(Sx/128, BHx), 256>>>();

    gemm_hmma<0><<<gg, 256>>>(3, 3, out, bo);       // out = ao @ Wo^T + bo
}

// round 15
// speedup vs baseline: 3.9098x; 1.0602x over previous
#include <cuda_runtime.h>
#include <cuda_bf16.h>
#include <stdint.h>

#define Bx 2
#define Sx 2048
#define Dx 1024
#define Hx 16
#define DKx 64
#define Mx (Bx*Sx)
#define BHx (Bx*Hx)
typedef __nv_bfloat16 bf16;

// ------------------------- device scratch (static) -------------------------
__device__ __align__(256) bf16 g_qh[(size_t)Mx*Dx],  g_ql[(size_t)Mx*Dx];
__device__ __align__(256) bf16 g_kh[(size_t)Mx*Dx],  g_kl[(size_t)Mx*Dx];
__device__ __align__(256) bf16 g_vh[(size_t)Mx*Dx],  g_vl[(size_t)Mx*Dx];
__device__ __align__(256) bf16 g_Wqh[(size_t)Dx*Dx], g_Wql[(size_t)Dx*Dx];
__device__ __align__(256) bf16 g_Wkh[(size_t)Dx*Dx], g_Wkl[(size_t)Dx*Dx];
__device__ __align__(256) bf16 g_Wvh[(size_t)Dx*Dx], g_Wvl[(size_t)Dx*Dx];
__device__ __align__(256) bf16 g_Woh[(size_t)Dx*Dx], g_Wol[(size_t)Dx*Dx];
__device__ __align__(256) bf16 g_q2h[(size_t)BHx*Sx*DKx], g_q2l[(size_t)BHx*Sx*DKx];
__device__ __align__(256) bf16 g_k2h[(size_t)BHx*Sx*DKx], g_k2l[(size_t)BHx*Sx*DKx];
__device__ __align__(256) bf16 g_v2h[(size_t)BHx*Sx*DKx], g_v2l[(size_t)BHx*Sx*DKx];
__device__ __align__(256) bf16 g_aoh[(size_t)Mx*Dx], g_aol[(size_t)Mx*Dx];

// ------------------------------- helpers -----------------------------------
__device__ __forceinline__ uint32_t s2u(const void* p){
    uint32_t a;
    asm("{ .reg .u64 t; cvta.to.shared.u64 t, %1; cvt.u32.u64 %0, t; }" : "=r"(a) : "l"(p));
    return a;
}
__device__ __forceinline__ uint32_t swz(uint32_t o){ return o ^ ((o >> 3) & 0x70); }
__device__ __forceinline__ uint32_t packbf(float x, float y){
    __nv_bfloat162 t = __floats2bfloat162_rn(x, y);
    return *reinterpret_cast<uint32_t*>(&t);
}
__device__ __forceinline__ float resid(float x){
    return x - __bfloat162float(__float2bfloat16(x));
}
__device__ __forceinline__ float exp2p(float t){
    t = fmaxf(t, -100.f);
    float r = rintf(t);
    float f = t - r;
    float p = 1.3333558e-3f;
    p = fmaf(p, f, 9.6181291e-3f);
    p = fmaf(p, f, 5.5504109e-2f);
    p = fmaf(p, f, 2.4022651e-1f);
    p = fmaf(p, f, 6.9314718e-1f);
    p = fmaf(p, f, 1.0f);
    int e = (int)r;
    return p * __int_as_float((e + 127) << 23);
}
__device__ __forceinline__ void ldsm4(uint32_t* r, uint32_t a){
    asm volatile("ldmatrix.sync.aligned.m8n8.x4.shared.b16 {%0,%1,%2,%3}, [%4];"
                 : "=r"(r[0]), "=r"(r[1]), "=r"(r[2]), "=r"(r[3]) : "r"(a));
}
__device__ __forceinline__ void ldsm4t(uint32_t* r, uint32_t a){
    asm volatile("ldmatrix.sync.aligned.m8n8.x4.trans.shared.b16 {%0,%1,%2,%3}, [%4];"
                 : "=r"(r[0]), "=r"(r[1]), "=r"(r[2]), "=r"(r[3]) : "r"(a));
}
__device__ __forceinline__ void mma16816(float* c, const uint32_t* a, const uint32_t* b){
    asm volatile("mma.sync.aligned.m16n8k16.row.col.f32.bf16.bf16.f32 "
                 "{%0,%1,%2,%3}, {%4,%5,%6,%7}, {%8,%9}, {%0,%1,%2,%3};"
                 : "+f"(c[0]), "+f"(c[1]), "+f"(c[2]), "+f"(c[3])
                 : "r"(a[0]), "r"(a[1]), "r"(a[2]), "r"(a[3]), "r"(b[0]), "r"(b[1]));
}
__device__ __forceinline__ void cpa(uint32_t dst, const void* src){
    asm volatile("cp.async.cg.shared.global [%0], [%1], 16;" :: "r"(dst), "l"(src));
}
#define CP_COMMIT() asm volatile("cp.async.commit_group;" ::: "memory")
#define CP_WAIT2()  asm volatile("cp.async.wait_group 2;" ::: "memory")
#define CP_WAIT1()  asm volatile("cp.async.wait_group 1;" ::: "memory")
#define CP_WAIT0()  asm volatile("cp.async.wait_group 0;" ::: "memory")

// ----------------------- fp32 -> (hi, lo) bf16 split (all tensors) ----------
__global__ void __launch_bounds__(256) split_all(
    const float4* __restrict__ v, const float4* __restrict__ k, const float4* __restrict__ q,
    const float4* __restrict__ wq, const float4* __restrict__ wk,
    const float4* __restrict__ wv, const float4* __restrict__ wo)
{
    int sel = blockIdx.y;
    int i = blockIdx.x * 256 + threadIdx.x;
    const float4* src; bf16 *H, *L; int n4;
    switch (sel){
        case 0: src=v;  H=g_vh;  L=g_vl;  n4=Mx*Dx/4; break;
        case 1: src=k;  H=g_kh;  L=g_kl;  n4=Mx*Dx/4; break;
        case 2: src=q;  H=g_qh;  L=g_ql;  n4=Mx*Dx/4; break;
        case 3: src=wq; H=g_Wqh; L=g_Wql; n4=Dx*Dx/4; break;
        case 4: src=wk; H=g_Wkh; L=g_Wkl; n4=Dx*Dx/4; break;
        case 5: src=wv; H=g_Wvh; L=g_Wvl; n4=Dx*Dx/4; break;
        default:src=wo; H=g_Woh; L=g_Wol; n4=Dx*Dx/4; break;
    }
    if (i >= n4) return;
    float4 x = src[i];
    bf16 h0 = __float2bfloat16(x.x), h1 = __float2bfloat16(x.y);
    bf16 h2 = __float2bfloat16(x.z), h3 = __float2bfloat16(x.w);
    __nv_bfloat162* Hp = (__nv_bfloat162*)H;
    __nv_bfloat162* Lp = (__nv_bfloat162*)L;
    __nv_bfloat162 t;
    t.x = h0; t.y = h1; Hp[i*2+0] = t;
    t.x = h2; t.y = h3; Hp[i*2+1] = t;
    t.x = __float2bfloat16(x.x - __bfloat162float(h0));
    t.y = __float2bfloat16(x.y - __bfloat162float(h1)); Lp[i*2+0] = t;
    t.x = __float2bfloat16(x.z - __bfloat162float(h2));
    t.y = __float2bfloat16(x.w - __bfloat162float(h3)); Lp[i*2+1] = t;
}

// ----- split-bf16 HMMA GEMM: C = A[4096,1024] @ W[1024,1024]^T (+bias) ------
// CTA tile 128x64, K-chunk 32, cp.async 2-stage. 8 warps (4x2), warp 32x32.
// MODE 1: merged projections, grid.z selects (q,k,v); split per-head out.
// MODE 0: out = ao @ Wo^T + bias, fp32 row-major.
template<int MODE>
__global__ void __launch_bounds__(256,2) gemm_hmma(
    const float* __restrict__ bias0, const float* __restrict__ bias1,
    const float* __restrict__ bias2, float* __restrict__ Cf)
{
    __shared__ __align__(1024) char sm[49152];
    const int tid = threadIdx.x, wid = tid >> 5, lane = tid & 31;
    const int row0 = blockIdx.x * 128, col0 = blockIdx.y * 64;
    const int z = (MODE == 1) ? blockIdx.z : 3;
    const uint32_t sb = s2u(sm);

    const bf16 *Ah, *Al, *Bh, *Bl;
    switch (z){
        case 0: Ah = g_qh;  Al = g_ql;  Bh = g_Wqh; Bl = g_Wql; break;
        case 1: Ah = g_kh;  Al = g_kl;  Bh = g_Wkh; Bl = g_Wkl; break;
        case 2: Ah = g_vh;  Al = g_vl;  Bh = g_Wvh; Bl = g_Wvl; break;
        default:Ah = g_aoh; Al = g_aol; Bh = g_Woh; Bl = g_Wol; break;
    }
    const float* bias = (z == 0) ? bias0 : (z == 1) ? bias1 : bias2;
    bf16 *Ch = nullptr, *Cl = nullptr;
    if (MODE == 1){
        switch (z){
            case 0: Ch = g_q2h; Cl = g_q2l; break;
            case 1: Ch = g_k2h; Cl = g_k2l; break;
            default:Ch = g_v2h; Cl = g_v2l; break;
        }
    } else {
        bias = bias0;
    }

    const int wm = wid >> 1, wn = wid & 1;
    const uint32_t la15 = lane & 15, lb7 = lane & 7;
    const uint32_t x0a = ((lane >> 4) & 1) * 16;
    const uint32_t xb  = ((lane >> 3) & 3) * 16;

    float acc[2][4][4];
    #pragma unroll
    for (int mi = 0; mi < 2; mi++)
        #pragma unroll
        for (int ni = 0; ni < 4; ni++)
            #pragma unroll
            for (int j = 0; j < 4; j++) acc[mi][ni][j] = 0.f;

    auto load_stage = [&](int st, int kc){
        const int k0 = kc * 32;
        const uint32_t base = sb + (uint32_t)st * 24576;
        #pragma unroll
        for (int it = 0; it < 4; it++){
            int id = tid + it*256;
            int r = id >> 3, vv = id & 7, hv = vv >> 2, ci = vv & 3;
            const bf16* src = hv ? Al : Ah;
            cpa(base + swz((uint32_t)(r*128 + hv*64 + ci*16)),
                src + (size_t)(row0 + r)*1024 + k0 + ci*8);
        }
        #pragma unroll
        for (int it = 0; it < 2; it++){
            int id = tid + it*256;
            int r = id >> 3, vv = id & 7, hv = vv >> 2, ci = vv & 3;
            const bf16* src = hv ? Bl : Bh;
            cpa(base + 16384 + swz((uint32_t)(r*128 + hv*64 + ci*16)),
                src + (size_t)(col0 + r)*1024 + k0 + ci*8);
        }
    };

    load_stage(0, 0); CP_COMMIT();
    for (int ci = 0; ci < 32; ci++){
        if (ci + 1 < 32) load_stage((ci+1) & 1, ci+1);
        CP_COMMIT();
        CP_WAIT1();
        __syncthreads();
        const uint32_t ta = sb + (uint32_t)(ci & 1) * 24576;
        const uint32_t tb = ta + 16384;

        uint32_t Bfh[4][4], Bfl[4][4];
        #pragma unroll
        for (int ni = 0; ni < 4; ni++){
            uint32_t rowb = wn*32 + ni*8 + lb7;
            uint32_t mask = (rowb & 7) << 4;
            uint32_t rb = tb + rowb*128;
            ldsm4(Bfh[ni], rb + (xb ^ mask));
            ldsm4(Bfl[ni], rb + ((64 + xb) ^ mask));
        }
        #pragma unroll
        for (int mi = 0; mi < 2; mi++){
            uint32_t rowa = wm*32 + mi*16 + la15;
            uint32_t maska = (rowa & 7) << 4;
            uint32_t rba = ta + rowa*128;
            #pragma unroll
            for (int ks = 0; ks < 2; ks++){
                uint32_t Ahf[4], Alf[4];
                uint32_t off = (uint32_t)ks*32 + x0a;
                ldsm4(Ahf, rba + (off ^ maska));
                ldsm4(Alf, rba + ((64 + off) ^ maska));
                // product-major: same-acc distance = 4 MMAs
                #pragma unroll
                for (int ni = 0; ni < 4; ni++) mma16816(acc[mi][ni], Ahf, &Bfh[ni][ks*2]);
                #pragma unroll
                for (int ni = 0; ni < 4; ni++) mma16816(acc[mi][ni], Ahf, &Bfl[ni][ks*2]);
                #pragma unroll
                for (int ni = 0; ni < 4; ni++) mma16816(acc[mi][ni], Alf, &Bfh[ni][ks*2]);
            }
        }
        __syncthreads();
    }
    CP_WAIT0();
    __syncthreads();

    float* smf = (float*)sm;
    #pragma unroll
    for (int mi = 0; mi < 2; mi++)
        #pragma unroll
        for (int ni = 0; ni < 4; ni++)
            #pragma unroll
            for (int j = 0; j < 4; j++){
                int rr = wm*32 + mi*16 + (lane >> 2) + 8*(j >> 1);
                int cc = wn*32 + ni*8 + 2*(lane & 3) + (j & 1);
                smf[rr*68 + cc] = acc[mi][ni][j];
            }
    __syncthreads();
    if (MODE == 0){
        #pragma unroll
        for (int it = 0; it < 8; it++){
            int id = tid + it*256;
            int r = id >> 4, c4 = (id & 15)*4;
            int gr = row0 + r, gc = col0 + c4;
            float4 o;
            o.x = smf[r*68+c4]   + bias[gc];
            o.y = smf[r*68+c4+1] + bias[gc+1];
            o.z = smf[r*68+c4+2] + bias[gc+2];
            o.w = smf[r*68+c4+3] + bias[gc+3];
            *(float4*)(Cf + (size_t)gr*1024 + gc) = o;
        }
    } else {
        #pragma unroll
        for (int it = 0; it < 16; it++){
            int id = tid + it*256;
            int r = id >> 5, c2 = (id & 31)*2;
            int gr = row0 + r, gc = col0 + c2;
            float x = smf[r*68+c2]   + bias[gc];
            float y = smf[r*68+c2+1] + bias[gc+1];
            int b_ = gr >> 11, s_ = gr & 2047;
            int h_ = gc >> 6,  dk = gc & 63;
            size_t g = (((size_t)(b_*Hx + h_))*Sx + s_)*DKx + dk;
            __nv_bfloat162 th, tl;
            th.x = __float2bfloat16(x); th.y = __float2bfloat16(y);
            tl.x = __float2bfloat16(x - __bfloat162float(th.x));
            tl.y = __float2bfloat16(y - __bfloat162float(th.y));
            *(__nv_bfloat162*)(Ch + g) = th;
            *(__nv_bfloat162*)(Cl + g) = tl;
        }
    }
}

// ------------------- flash attention (HMMA, split-bf16) ---------------------
// Role swap: scores = v2 @ k2^T / 8; out = softmax @ q2.
// CTA: 128 q-rows of one (b,h); KV chunks of 64.
// K double-buffered (2 x 16KB), V single-buffered (16KB) = 48KB.
__global__ void __launch_bounds__(256,2) flash_kernel(){
    __shared__ __align__(1024) char sm[49152];
    const int tid = threadIdx.x, wid = tid >> 5, lane = tid & 31;
    const int bh = blockIdx.y, row0 = blockIdx.x * 128;
    const int b = bh >> 4, h = bh & 15;
    const uint32_t sb = s2u(sm);
    const size_t hb = (size_t)bh * Sx * DKx;
    const bf16* Qh_g = g_v2h + hb; const bf16* Ql_g = g_v2l + hb;
    const bf16* Kh_g = g_k2h + hb; const bf16* Kl_g = g_k2l + hb;
    const bf16* Vh_g = g_q2h + hb; const bf16* Vl_g = g_q2l + hb;

    const uint32_t la15 = lane & 15, lb7 = lane & 7;
    const uint32_t x0a = ((lane >> 4) & 1) * 16;
    const uint32_t xb  = ((lane >> 3) & 3) * 16;

    // ---- Q load + fragment extraction ----
    #pragma unroll
    for (int it = 0; it < 8; it++){
        int id = tid + it*256;
        int half = id >> 10, i2 = id & 1023;
        int r = i2 >> 3, c = i2 & 7;
        const bf16* src = half ? Ql_g : Qh_g;
        cpa(sb + (uint32_t)half*16384 + swz((uint32_t)(r*128 + c*16)),
            src + (size_t)(row0 + r)*DKx + c*8);
    }
    CP_COMMIT(); CP_WAIT0();
    __syncthreads();
    uint32_t qh_f[4][4], ql_f[4][4];
    {
        uint32_t lr = (uint32_t)wid*16 + la15;
        uint32_t qmask = (lr & 7) << 4;
        uint32_t qb = sb + lr*128;
        #pragma unroll
        for (int ks = 0; ks < 4; ks++){
            uint32_t off = (uint32_t)ks*32 + x0a;
            ldsm4(qh_f[ks], qb +         (off ^ qmask));
            ldsm4(ql_f[ks], qb + 16384 + (off ^ qmask));
        }
    }
    __syncthreads();

    float m0 = -1e30f, m1 = -1e30f, l0 = 0.f, l1 = 0.f;
    float oacc[8][4];
    #pragma unroll
    for (int n = 0; n < 8; n++){ oacc[n][0]=0.f; oacc[n][1]=0.f; oacc[n][2]=0.f; oacc[n][3]=0.f; }
    const float cs = 0.18033688f;   // 0.125 * log2(e)

    auto load_k = [&](int st, int kc){
        const int r0k = kc * 64;
        const uint32_t base = sb + (uint32_t)st * 16384;
        #pragma unroll
        for (int it = 0; it < 4; it++){
            int id = tid + it*256;
            int half = id >> 9, i2 = id & 511;
            int r = i2 >> 3, c = i2 & 7;
            const bf16* src = half ? Kl_g : Kh_g;
            cpa(base + (uint32_t)half*8192 + swz((uint32_t)(r*128 + c*16)),
                src + (size_t)(r0k + r)*DKx + c*8);
        }
    };
    auto load_v = [&](int kc){
        const int r0k = kc * 64;
        #pragma unroll
        for (int it = 0; it < 4; it++){
            int id = tid + it*256;
            int half = id >> 9, i2 = id & 511;
            int r = i2 >> 3, c = i2 & 7;
            const bf16* src = half ? Vl_g : Vh_g;
            cpa(sb + 32768 + (uint32_t)half*8192 + swz((uint32_t)(r*128 + c*16)),
                src + (size_t)(r0k + r)*DKx + c*8);
        }
    };

    load_k(0, 0); CP_COMMIT();
    for (int ci = 0; ci < 32; ci++){
        load_v(ci); CP_COMMIT();
        load_k((ci+1) & 1, (ci+1 < 32) ? ci+1 : 0); CP_COMMIT();
        CP_WAIT2();                 // K[ci] ready (pending: V[ci], K[ci+1])
        __syncthreads();
        const uint32_t st = sb + (uint32_t)(ci & 1) * 16384;

        // ---- S = Q @ K^T (3 split products), 64 key rows ----
        float sacc[8][4];
        #pragma unroll
        for (int n = 0; n < 8; n++){ sacc[n][0]=0.f; sacc[n][1]=0.f; sacc[n][2]=0.f; sacc[n][3]=0.f; }
        #pragma unroll
        for (int n = 0; n < 8; n++){
            uint32_t rn = (uint32_t)n*8 + lb7;
            uint32_t mask = (rn & 7) << 4;
            uint32_t rb = st + rn*128;
            uint32_t bh0[4], bh1[4], bl0[4], bl1[4];
            ldsm4(bh0, rb +        (xb ^ mask));
            ldsm4(bh1, rb +        ((64 + xb) ^ mask));
            ldsm4(bl0, rb + 8192 + (xb ^ mask));
            ldsm4(bl1, rb + 8192 + ((64 + xb) ^ mask));
            mma16816(sacc[n], qh_f[0], bh0+0);
            mma16816(sacc[n], qh_f[1], bh0+2);
            mma16816(sacc[n], qh_f[2], bh1+0);
            mma16816(sacc[n], qh_f[3], bh1+2);
            mma16816(sacc[n], qh_f[0], bl0+0);
            mma16816(sacc[n], qh_f[1], bl0+2);
            mma16816(sacc[n], qh_f[2], bl1+0);
            mma16816(sacc[n], qh_f[3], bl1+2);
            mma16816(sacc[n], ql_f[0], bh0+0);
            mma16816(sacc[n], ql_f[1], bh0+2);
            mma16816(sacc[n], ql_f[2], bh1+0);
            mma16816(sacc[n], ql_f[3], bh1+2);
        }

        // ---- online softmax ----
        float mx0 = sacc[0][0], mx1 = sacc[0][2];
        #pragma unroll
        for (int n = 0; n < 8; n++){
            mx0 = fmaxf(mx0, fmaxf(sacc[n][0], sacc[n][1]));
            mx1 = fmaxf(mx1, fmaxf(sacc[n][2], sacc[n][3]));
        }
        mx0 = fmaxf(mx0, __shfl_xor_sync(0xffffffffu, mx0, 1));
        mx0 = fmaxf(mx0, __shfl_xor_sync(0xffffffffu, mx0, 2));
        mx1 = fmaxf(mx1, __shfl_xor_sync(0xffffffffu, mx1, 1));
        mx1 = fmaxf(mx1, __shfl_xor_sync(0xffffffffu, mx1, 2));
        float mn0 = fmaxf(m0, mx0), mn1 = fmaxf(m1, mx1);
        float al0 = exp2p((m0 - mn0)*cs), al1 = exp2p((m1 - mn1)*cs);
        m0 = mn0; m1 = mn1;
        float s0 = 0.f, s1 = 0.f;
        #pragma unroll
        for (int n = 0; n < 8; n++){
            sacc[n][0] = exp2p((sacc[n][0] - mn0)*cs); s0 += sacc[n][0];
            sacc[n][1] = exp2p((sacc[n][1] - mn0)*cs); s0 += sacc[n][1];
            sacc[n][2] = exp2p((sacc[n][2] - mn1)*cs); s1 += sacc[n][2];
            sacc[n][3] = exp2p((sacc[n][3] - mn1)*cs); s1 += sacc[n][3];
        }
        s0 += __shfl_xor_sync(0xffffffffu, s0, 1);
        s0 += __shfl_xor_sync(0xffffffffu, s0, 2);
        s1 += __shfl_xor_sync(0xffffffffu, s1, 1);
        s1 += __shfl_xor_sync(0xffffffffu, s1, 2);
        l0 = l0*al0 + s0; l1 = l1*al1 + s1;
        #pragma unroll
        for (int n = 0; n < 8; n++){
            oacc[n][0] *= al0; oacc[n][1] *= al0;
            oacc[n][2] *= al1; oacc[n][3] *= al1;
        }

        CP_WAIT1();                 // V[ci] ready (pending: K[ci+1])
        __syncthreads();

        // ---- O += P @ V (two 32-key halves) ----
        #pragma unroll
        for (int kp = 0; kp < 2; kp++){
            uint32_t pah[2][4], pal[2][4];
            #pragma unroll
            for (int kk = 0; kk < 2; kk++){
                int n0 = (kp*2 + kk)*2, n1 = n0 + 1;
                pah[kk][0] = packbf(sacc[n0][0], sacc[n0][1]);
                pah[kk][1] = packbf(sacc[n0][2], sacc[n0][3]);
                pah[kk][2] = packbf(sacc[n1][0], sacc[n1][1]);
                pah[kk][3] = packbf(sacc[n1][2], sacc[n1][3]);
                pal[kk][0] = packbf(resid(sacc[n0][0]), resid(sacc[n0][1]));
                pal[kk][1] = packbf(resid(sacc[n0][2]), resid(sacc[n0][3]));
                pal[kk][2] = packbf(resid(sacc[n1][0]), resid(sacc[n1][1]));
                pal[kk][3] = packbf(resid(sacc[n1][2]), resid(sacc[n1][3]));
            }
            uint32_t vrow = (uint32_t)kp*32 + lane;
            uint32_t vmask = (vrow & 7) << 4;
            uint32_t vbh = sb + 32768 + vrow*128;
            uint32_t vbl = sb + 40960 + vrow*128;
            #pragma unroll
            for (int nd = 0; nd < 8; nd++){
                uint32_t bvh[4], bvl[4];
                uint32_t off = ((uint32_t)nd*16) ^ vmask;
                ldsm4t(bvh, vbh + off);
                ldsm4t(bvl, vbl + off);
                mma16816(oacc[nd], pah[0], bvh+0);
                mma16816(oacc[nd], pah[0], bvl+0);
                mma16816(oacc[nd], pal[0], bvh+0);
                mma16816(oacc[nd], pah[1], bvh+2);
                mma16816(oacc[nd], pah[1], bvl+2);
                mma16816(oacc[nd], pal[1], bvh+2);
            }
        }
        __syncthreads();
    }
    CP_WAIT0();
    __syncthreads();

    // ---- epilogue: normalize, two 64-row passes, split concat writes ----
    float inv0 = 1.f / l0, inv1 = 1.f / l1;
    float* smf = (float*)sm;
    #pragma unroll
    for (int hf = 0; hf < 2; hf++){
        if ((wid >> 2) == hf){
            int r0l = (wid & 3)*16 + (lane >> 2), r1l = r0l + 8;
            #pragma unroll
            for (int nd = 0; nd < 8; nd++){
                int cb = nd*8 + 2*(lane & 3);
                smf[r0l*68 + cb]   = oacc[nd][0]*inv0;
                smf[r0l*68 + cb+1] = oacc[nd][1]*inv0;
                smf[r1l*68 + cb]   = oacc[nd][2]*inv1;
                smf[r1l*68 + cb+1] = oacc[nd][3]*inv1;
            }
        }
        __syncthreads();
        #pragma unroll
        for (int it = 0; it < 8; it++){
            int id = tid + it*256;
            int r = id >> 5, c2 = (id & 31)*2;
            int gr = row0 + hf*64 + r;
            float x = smf[r*68 + c2], y = smf[r*68 + c2 + 1];
            size_t g = ((size_t)(b*Sx + gr))*Dx + h*DKx + c2;
            __nv_bfloat162 th, tl;
            th.x = __float2bfloat16(x); th.y = __float2bfloat16(y);
            tl.x = __float2bfloat16(x - __bfloat162float(th.x));
            tl.y = __float2bfloat16(y - __bfloat162float(th.y));
            *(__nv_bfloat162*)(g_aoh + g) = th;
            *(__nv_bfloat162*)(g_aol + g) = tl;
        }
        __syncthreads();
    }
}

// --------------------------------- launch -----------------------------------
extern "C" void kernel_launch(void* const* d_in, const int* in_sizes, int n_in,
                              void* d_out, int out_size)
{
    const float* bq = (const float*)d_in[4];
    const float* bk = (const float*)d_in[6];
    const float* bv = (const float*)d_in[8];
    const float* bo = (const float*)d_in[10];
    float* out = (float*)d_out;

    split_all<<<dim3(Mx*Dx/4/256, 7), 256>>>(
        (const float4*)d_in[0], (const float4*)d_in[1], (const float4*)d_in[2],
        (const float4*)d_in[3], (const float4*)d_in[5], (const float4*)d_in[7],
        (const float4*)d_in[9]);

    // all three projections in one launch (z = q/k/v)
    gemm_hmma<1><<<dim3(Mx/128, Dx/64, 3), 256>>>(bq, bk, bv, nullptr);

    flash_kernel<<<dim3(Sx/128, BHx), 256>>>();

    gemm_hmma<0><<<dim3(Mx/128, Dx/64, 1), 256>>>(bo, bo, bo, out);
}

// round 16
// speedup vs baseline: 4.1098x; 1.0511x over previous
#include <cuda_runtime.h>
#include <cuda_bf16.h>
#include <stdint.h>

#define Bx 2
#define Sx 2048
#define Dx 1024
#define Hx 16
#define DKx 64
#define Mx (Bx*Sx)
#define BHx (Bx*Hx)
typedef __nv_bfloat16 bf16;

// ------------------------- device scratch (static) -------------------------
__device__ __align__(256) bf16 g_qh[(size_t)Mx*Dx],  g_ql[(size_t)Mx*Dx];
__device__ __align__(256) bf16 g_kh[(size_t)Mx*Dx],  g_kl[(size_t)Mx*Dx];
__device__ __align__(256) bf16 g_vh[(size_t)Mx*Dx],  g_vl[(size_t)Mx*Dx];
__device__ __align__(256) bf16 g_Wqh[(size_t)Dx*Dx], g_Wql[(size_t)Dx*Dx];
__device__ __align__(256) bf16 g_Wkh[(size_t)Dx*Dx], g_Wkl[(size_t)Dx*Dx];
__device__ __align__(256) bf16 g_Wvh[(size_t)Dx*Dx], g_Wvl[(size_t)Dx*Dx];
__device__ __align__(256) bf16 g_Woh[(size_t)Dx*Dx], g_Wol[(size_t)Dx*Dx];
__device__ __align__(256) bf16 g_q2h[(size_t)BHx*Sx*DKx], g_q2l[(size_t)BHx*Sx*DKx];
__device__ __align__(256) bf16 g_k2h[(size_t)BHx*Sx*DKx], g_k2l[(size_t)BHx*Sx*DKx];
__device__ __align__(256) bf16 g_v2h[(size_t)BHx*Sx*DKx], g_v2l[(size_t)BHx*Sx*DKx];
__device__ __align__(256) bf16 g_aoh[(size_t)Mx*Dx], g_aol[(size_t)Mx*Dx];

// ------------------------------- helpers -----------------------------------
__device__ __forceinline__ uint32_t s2u(const void* p){
    uint32_t a;
    asm("{ .reg .u64 t; cvta.to.shared.u64 t, %1; cvt.u32.u64 %0, t; }" : "=r"(a) : "l"(p));
    return a;
}
__device__ __forceinline__ uint32_t swz(uint32_t o){ return o ^ ((o >> 3) & 0x70); }
__device__ __forceinline__ uint32_t packbf(float x, float y){
    __nv_bfloat162 t = __floats2bfloat162_rn(x, y);
    return *reinterpret_cast<uint32_t*>(&t);
}
__device__ __forceinline__ float resid(float x){
    return x - __bfloat162float(__float2bfloat16(x));
}
__device__ __forceinline__ float exp2p(float t){
    t = fmaxf(t, -100.f);
    float r = rintf(t);
    float f = t - r;
    float p = 1.3333558e-3f;
    p = fmaf(p, f, 9.6181291e-3f);
    p = fmaf(p, f, 5.5504109e-2f);
    p = fmaf(p, f, 2.4022651e-1f);
    p = fmaf(p, f, 6.9314718e-1f);
    p = fmaf(p, f, 1.0f);
    int e = (int)r;
    return p * __int_as_float((e + 127) << 23);
}
__device__ __forceinline__ void ldsm4(uint32_t* r, uint32_t a){
    asm volatile("ldmatrix.sync.aligned.m8n8.x4.shared.b16 {%0,%1,%2,%3}, [%4];"
                 : "=r"(r[0]), "=r"(r[1]), "=r"(r[2]), "=r"(r[3]) : "r"(a));
}
__device__ __forceinline__ void ldsm4t(uint32_t* r, uint32_t a){
    asm volatile("ldmatrix.sync.aligned.m8n8.x4.trans.shared.b16 {%0,%1,%2,%3}, [%4];"
                 : "=r"(r[0]), "=r"(r[1]), "=r"(r[2]), "=r"(r[3]) : "r"(a));
}
__device__ __forceinline__ void mma16816(float* c, const uint32_t* a, const uint32_t* b){
    asm volatile("mma.sync.aligned.m16n8k16.row.col.f32.bf16.bf16.f32 "
                 "{%0,%1,%2,%3}, {%4,%5,%6,%7}, {%8,%9}, {%0,%1,%2,%3};"
                 : "+f"(c[0]), "+f"(c[1]), "+f"(c[2]), "+f"(c[3])
                 : "r"(a[0]), "r"(a[1]), "r"(a[2]), "r"(a[3]), "r"(b[0]), "r"(b[1]));
}
__device__ __forceinline__ void cpa(uint32_t dst, const void* src){
    asm volatile("cp.async.cg.shared.global [%0], [%1], 16;" :: "r"(dst), "l"(src));
}
#define CP_COMMIT() asm volatile("cp.async.commit_group;" ::: "memory")
#define CP_WAIT1()  asm volatile("cp.async.wait_group 1;" ::: "memory")
#define CP_WAIT0()  asm volatile("cp.async.wait_group 0;" ::: "memory")

// ----------------------- fp32 -> (hi, lo) bf16 split (all tensors) ----------
__global__ void __launch_bounds__(256) split_all(
    const float4* __restrict__ v, const float4* __restrict__ k, const float4* __restrict__ q,
    const float4* __restrict__ wq, const float4* __restrict__ wk,
    const float4* __restrict__ wv, const float4* __restrict__ wo)
{
    int sel = blockIdx.y;
    int i = blockIdx.x * 256 + threadIdx.x;
    const float4* src; bf16 *H, *L; int n4;
    switch (sel){
        case 0: src=v;  H=g_vh;  L=g_vl;  n4=Mx*Dx/4; break;
        case 1: src=k;  H=g_kh;  L=g_kl;  n4=Mx*Dx/4; break;
        case 2: src=q;  H=g_qh;  L=g_ql;  n4=Mx*Dx/4; break;
        case 3: src=wq; H=g_Wqh; L=g_Wql; n4=Dx*Dx/4; break;
        case 4: src=wk; H=g_Wkh; L=g_Wkl; n4=Dx*Dx/4; break;
        case 5: src=wv; H=g_Wvh; L=g_Wvl; n4=Dx*Dx/4; break;
        default:src=wo; H=g_Woh; L=g_Wol; n4=Dx*Dx/4; break;
    }
    if (i >= n4) return;
    float4 x = src[i];
    bf16 h0 = __float2bfloat16(x.x), h1 = __float2bfloat16(x.y);
    bf16 h2 = __float2bfloat16(x.z), h3 = __float2bfloat16(x.w);
    __nv_bfloat162* Hp = (__nv_bfloat162*)H;
    __nv_bfloat162* Lp = (__nv_bfloat162*)L;
    __nv_bfloat162 t;
    t.x = h0; t.y = h1; Hp[i*2+0] = t;
    t.x = h2; t.y = h3; Hp[i*2+1] = t;
    t.x = __float2bfloat16(x.x - __bfloat162float(h0));
    t.y = __float2bfloat16(x.y - __bfloat162float(h1)); Lp[i*2+0] = t;
    t.x = __float2bfloat16(x.z - __bfloat162float(h2));
    t.y = __float2bfloat16(x.w - __bfloat162float(h3)); Lp[i*2+1] = t;
}

// ----- split-bf16 HMMA GEMM: C = A @ W^T (+bias), emulated fp32 -------------
// CTA tile 64x64, 128 threads (4 warps, warp 32x32), K-chunk 32,
// 3-stage cp.async, ONE __syncthreads per chunk. 4 CTAs/SM.
// MODE 1: merged projections (grid.z = q/k/v), split per-head out.
// MODE 0: out = ao @ Wo^T + bias, fp32 row-major.
template<int MODE>
__global__ void __launch_bounds__(128,4) gemm_hmma(
    const float* __restrict__ bias0, const float* __restrict__ bias1,
    const float* __restrict__ bias2, float* __restrict__ Cf)
{
    __shared__ __align__(1024) char sm[49152];   // 3 stages x (A 8K + B 8K)
    const int tid = threadIdx.x, wid = tid >> 5, lane = tid & 31;
    const int row0 = blockIdx.x * 64, col0 = blockIdx.y * 64;
    const int z = (MODE == 1) ? blockIdx.z : 3;
    const uint32_t sb = s2u(sm);

    const bf16 *Ah, *Al, *Bh, *Bl;
    switch (z){
        case 0: Ah = g_qh;  Al = g_ql;  Bh = g_Wqh; Bl = g_Wql; break;
        case 1: Ah = g_kh;  Al = g_kl;  Bh = g_Wkh; Bl = g_Wkl; break;
        case 2: Ah = g_vh;  Al = g_vl;  Bh = g_Wvh; Bl = g_Wvl; break;
        default:Ah = g_aoh; Al = g_aol; Bh = g_Woh; Bl = g_Wol; break;
    }
    const float* bias = (z == 0) ? bias0 : (z == 1) ? bias1 : (z == 2) ? bias2 : bias0;
    bf16 *Ch = nullptr, *Cl = nullptr;
    if (MODE == 1){
        switch (z){
            case 0: Ch = g_q2h; Cl = g_q2l; break;
            case 1: Ch = g_k2h; Cl = g_k2l; break;
            default:Ch = g_v2h; Cl = g_v2l; break;
        }
    }

    const int wm = wid >> 1, wn = wid & 1;
    const uint32_t la15 = lane & 15, lb7 = lane & 7;
    const uint32_t x0a = ((lane >> 4) & 1) * 16;
    const uint32_t xb  = ((lane >> 3) & 3) * 16;

    float acc[2][4][4];
    #pragma unroll
    for (int mi = 0; mi < 2; mi++)
        #pragma unroll
        for (int ni = 0; ni < 4; ni++)
            #pragma unroll
            for (int j = 0; j < 4; j++) acc[mi][ni][j] = 0.f;

    auto load_stage = [&](int st, int kc){
        const int k0 = kc * 32;
        const uint32_t base = sb + (uint32_t)st * 16384;
        #pragma unroll
        for (int it = 0; it < 4; it++){             // A: 512 lines
            int id = tid + it*128;
            int r = id >> 3, vv = id & 7, hv = vv >> 2, c2 = vv & 3;
            const bf16* src = hv ? Al : Ah;
            cpa(base + swz((uint32_t)(r*128 + hv*64 + c2*16)),
                src + (size_t)(row0 + r)*1024 + k0 + c2*8);
        }
        #pragma unroll
        for (int it = 0; it < 4; it++){             // B: 512 lines
            int id = tid + it*128;
            int r = id >> 3, vv = id & 7, hv = vv >> 2, c2 = vv & 3;
            const bf16* src = hv ? Bl : Bh;
            cpa(base + 8192 + swz((uint32_t)(r*128 + hv*64 + c2*16)),
                src + (size_t)(col0 + r)*1024 + k0 + c2*8);
        }
    };

    load_stage(0, 0); CP_COMMIT();
    load_stage(1, 1); CP_COMMIT();
    for (int ci = 0; ci < 32; ci++){
        CP_WAIT1();              // chunk ci complete (groups retire in order)
        __syncthreads();         // visibility; also proves slot (ci+2)%3 free
        int nc = ci + 2;
        if (nc < 32) load_stage(nc % 3, nc);
        CP_COMMIT();             // empty group in tail keeps wait counts valid
        const uint32_t ta = sb + (uint32_t)(ci % 3) * 16384;
        const uint32_t tb = ta + 8192;

        uint32_t Bfh[4][4], Bfl[4][4];
        #pragma unroll
        for (int ni = 0; ni < 4; ni++){
            uint32_t rowb = wn*32 + ni*8 + lb7;
            uint32_t mask = (rowb & 7) << 4;
            uint32_t rb = tb + rowb*128;
            ldsm4(Bfh[ni], rb + (xb ^ mask));
            ldsm4(Bfl[ni], rb + ((64 + xb) ^ mask));
        }
        #pragma unroll
        for (int mi = 0; mi < 2; mi++){
            uint32_t rowa = wm*32 + mi*16 + la15;
            uint32_t maska = (rowa & 7) << 4;
            uint32_t rba = ta + rowa*128;
            #pragma unroll
            for (int ks = 0; ks < 2; ks++){
                uint32_t Ahf[4], Alf[4];
                uint32_t off = (uint32_t)ks*32 + x0a;
                ldsm4(Ahf, rba + (off ^ maska));
                ldsm4(Alf, rba + ((64 + off) ^ maska));
                #pragma unroll
                for (int ni = 0; ni < 4; ni++) mma16816(acc[mi][ni], Ahf, &Bfh[ni][ks*2]);
                #pragma unroll
                for (int ni = 0; ni < 4; ni++) mma16816(acc[mi][ni], Ahf, &Bfl[ni][ks*2]);
                #pragma unroll
                for (int ni = 0; ni < 4; ni++) mma16816(acc[mi][ni], Alf, &Bfh[ni][ks*2]);
            }
        }
    }
    CP_WAIT0();
    __syncthreads();

    // epilogue: stage 64x64 tile [64][68], coalesced stores
    float* smf = (float*)sm;
    #pragma unroll
    for (int mi = 0; mi < 2; mi++)
        #pragma unroll
        for (int ni = 0; ni < 4; ni++)
            #pragma unroll
            for (int j = 0; j < 4; j++){
                int rr = wm*32 + mi*16 + (lane >> 2) + 8*(j >> 1);
                int cc = wn*32 + ni*8 + 2*(lane & 3) + (j & 1);
                smf[rr*68 + cc] = acc[mi][ni][j];
            }
    __syncthreads();
    if (MODE == 0){
        #pragma unroll
        for (int it = 0; it < 8; it++){
            int id = tid + it*128;                   // 1024 float4s
            int r = id >> 4, c4 = (id & 15)*4;
            int gr = row0 + r, gc = col0 + c4;
            float4 o;
            o.x = smf[r*68+c4]   + bias[gc];
            o.y = smf[r*68+c4+1] + bias[gc+1];
            o.z = smf[r*68+c4+2] + bias[gc+2];
            o.w = smf[r*68+c4+3] + bias[gc+3];
            *(float4*)(Cf + (size_t)gr*1024 + gc) = o;
        }
    } else {
        #pragma unroll
        for (int it = 0; it < 16; it++){
            int id = tid + it*128;                   // 2048 bf16x2 pairs
            int r = id >> 5, c2 = (id & 31)*2;
            int gr = row0 + r, gc = col0 + c2;
            float x = smf[r*68+c2]   + bias[gc];
            float y = smf[r*68+c2+1] + bias[gc+1];
            int b_ = gr >> 11, s_ = gr & 2047;
            int h_ = gc >> 6,  dk = gc & 63;
            size_t g = (((size_t)(b_*Hx + h_))*Sx + s_)*DKx + dk;
            __nv_bfloat162 th, tl;
            th.x = __float2bfloat16(x); th.y = __float2bfloat16(y);
            tl.x = __float2bfloat16(x - __bfloat162float(th.x));
            tl.y = __float2bfloat16(y - __bfloat162float(th.y));
            *(__nv_bfloat162*)(Ch + g) = th;
            *(__nv_bfloat162*)(Cl + g) = tl;
        }
    }
}

// ------------------- flash attention (HMMA, split-bf16) ---------------------
// Role swap: scores = v2 @ k2^T / 8; out = softmax @ q2.
// CTA: 128 q-rows of one (b,h); KV chunks of 64. K double-buffered (2x16KB),
// V single-buffered (16KB). TWO barriers per chunk (issue-after-barrier order).
__global__ void __launch_bounds__(256,2) flash_kernel(){
    __shared__ __align__(1024) char sm[49152];
    const int tid = threadIdx.x, wid = tid >> 5, lane = tid & 31;
    const int bh = blockIdx.y, row0 = blockIdx.x * 128;
    const int b = bh >> 4, h = bh & 15;
    const uint32_t sb = s2u(sm);
    const size_t hb = (size_t)bh * Sx * DKx;
    const bf16* Qh_g = g_v2h + hb; const bf16* Ql_g = g_v2l + hb;
    const bf16* Kh_g = g_k2h + hb; const bf16* Kl_g = g_k2l + hb;
    const bf16* Vh_g = g_q2h + hb; const bf16* Vl_g = g_q2l + hb;

    const uint32_t la15 = lane & 15, lb7 = lane & 7;
    const uint32_t x0a = ((lane >> 4) & 1) * 16;
    const uint32_t xb  = ((lane >> 3) & 3) * 16;

    // ---- Q load + fragment extraction ----
    #pragma unroll
    for (int it = 0; it < 8; it++){
        int id = tid + it*256;
        int half = id >> 10, i2 = id & 1023;
        int r = i2 >> 3, c = i2 & 7;
        const bf16* src = half ? Ql_g : Qh_g;
        cpa(sb + (uint32_t)half*16384 + swz((uint32_t)(r*128 + c*16)),
            src + (size_t)(row0 + r)*DKx + c*8);
    }
    CP_COMMIT(); CP_WAIT0();
    __syncthreads();
    uint32_t qh_f[4][4], ql_f[4][4];
    {
        uint32_t lr = (uint32_t)wid*16 + la15;
        uint32_t qmask = (lr & 7) << 4;
        uint32_t qb = sb + lr*128;
        #pragma unroll
        for (int ks = 0; ks < 4; ks++){
            uint32_t off = (uint32_t)ks*32 + x0a;
            ldsm4(qh_f[ks], qb +         (off ^ qmask));
            ldsm4(ql_f[ks], qb + 16384 + (off ^ qmask));
        }
    }
    __syncthreads();

    float m0 = -1e30f, m1 = -1e30f, l0 = 0.f, l1 = 0.f;
    float oacc[8][4];
    #pragma unroll
    for (int n = 0; n < 8; n++){ oacc[n][0]=0.f; oacc[n][1]=0.f; oacc[n][2]=0.f; oacc[n][3]=0.f; }
    const float cs = 0.18033688f;   // 0.125 * log2(e)

    auto load_k = [&](int st, int kc){
        const int r0k = kc * 64;
        const uint32_t base = sb + (uint32_t)st * 16384;
        #pragma unroll
        for (int it = 0; it < 4; it++){
            int id = tid + it*256;
            int half = id >> 9, i2 = id & 511;
            int r = i2 >> 3, c = i2 & 7;
            const bf16* src = half ? Kl_g : Kh_g;
            cpa(base + (uint32_t)half*8192 + swz((uint32_t)(r*128 + c*16)),
                src + (size_t)(r0k + r)*DKx + c*8);
        }
    };
    auto load_v = [&](int kc){
        const int r0k = kc * 64;
        #pragma unroll
        for (int it = 0; it < 4; it++){
            int id = tid + it*256;
            int half = id >> 9, i2 = id & 511;
            int r = i2 >> 3, c = i2 & 7;
            const bf16* src = half ? Vl_g : Vh_g;
            cpa(sb + 32768 + (uint32_t)half*8192 + swz((uint32_t)(r*128 + c*16)),
                src + (size_t)(r0k + r)*DKx + c*8);
        }
    };

    load_k(0, 0); CP_COMMIT();
    for (int ci = 0; ci < 32; ci++){
        CP_WAIT0();              // K[ci] ready
        __syncthreads();         // barrier A: K visible; V buffer free (PV[ci-1] done)
        load_v(ci); CP_COMMIT();
        if (ci + 1 < 32) load_k((ci+1) & 1, ci+1);
        CP_COMMIT();
        const uint32_t st = sb + (uint32_t)(ci & 1) * 16384;

        // ---- S = Q @ K^T (3 split products), 64 key rows ----
        float sacc[8][4];
        #pragma unroll
        for (int n = 0; n < 8; n++){ sacc[n][0]=0.f; sacc[n][1]=0.f; sacc[n][2]=0.f; sacc[n][3]=0.f; }
        #pragma unroll
        for (int n = 0; n < 8; n++){
            uint32_t rn = (uint32_t)n*8 + lb7;
            uint32_t mask = (rn & 7) << 4;
            uint32_t rb = st + rn*128;
            uint32_t bh0[4], bh1[4], bl0[4], bl1[4];
            ldsm4(bh0, rb +        (xb ^ mask));
            ldsm4(bh1, rb +        ((64 + xb) ^ mask));
            ldsm4(bl0, rb + 8192 + (xb ^ mask));
            ldsm4(bl1, rb + 8192 + ((64 + xb) ^ mask));
            mma16816(sacc[n], qh_f[0], bh0+0);
            mma16816(sacc[n], qh_f[1], bh0+2);
            mma16816(sacc[n], qh_f[2], bh1+0);
            mma16816(sacc[n], qh_f[3], bh1+2);
            mma16816(sacc[n], qh_f[0], bl0+0);
            mma16816(sacc[n], qh_f[1], bl0+2);
            mma16816(sacc[n], qh_f[2], bl1+0);
            mma16816(sacc[n], qh_f[3], bl1+2);
            mma16816(sacc[n], ql_f[0], bh0+0);
            mma16816(sacc[n], ql_f[1], bh0+2);
            mma16816(sacc[n], ql_f[2], bh1+0);
            mma16816(sacc[n], ql_f[3], bh1+2);
        }

        // ---- online softmax ----
        float mx0 = sacc[0][0], mx1 = sacc[0][2];
        #pragma unroll
        for (int n = 0; n < 8; n++){
            mx0 = fmaxf(mx0, fmaxf(sacc[n][0], sacc[n][1]));
            mx1 = fmaxf(mx1, fmaxf(sacc[n][2], sacc[n][3]));
        }
        mx0 = fmaxf(mx0, __shfl_xor_sync(0xffffffffu, mx0, 1));
        mx0 = fmaxf(mx0, __shfl_xor_sync(0xffffffffu, mx0, 2));
        mx1 = fmaxf(mx1, __shfl_xor_sync(0xffffffffu, mx1, 1));
        mx1 = fmaxf(mx1, __shfl_xor_sync(0xffffffffu, mx1, 2));
        float mn0 = fmaxf(m0, mx0), mn1 = fmaxf(m1, mx1);
        float al0 = exp2p((m0 - mn0)*cs), al1 = exp2p((m1 - mn1)*cs);
        m0 = mn0; m1 = mn1;
        float s0 = 0.f, s1 = 0.f;
        #pragma unroll
        for (int n = 0; n < 8; n++){
            sacc[n][0] = exp2p((sacc[n][0] - mn0)*cs); s0 += sacc[n][0];
            sacc[n][1] = exp2p((sacc[n][1] - mn0)*cs); s0 += sacc[n][1];
            sacc[n][2] = exp2p((sacc[n][2] - mn1)*cs); s1 += sacc[n][2];
            sacc[n][3] = exp2p((sacc[n][3] - mn1)*cs); s1 += sacc[n][3];
        }
        s0 += __shfl_xor_sync(0xffffffffu, s0, 1);
        s0 += __shfl_xor_sync(0xffffffffu, s0, 2);
        s1 += __shfl_xor_sync(0xffffffffu, s1, 1);
        s1 += __shfl_xor_sync(0xffffffffu, s1, 2);
        l0 = l0*al0 + s0; l1 = l1*al1 + s1;
        #pragma unroll
        for (int n = 0; n < 8; n++){
            oacc[n][0] *= al0; oacc[n][1] *= al0;
            oacc[n][2] *= al1; oacc[n][3] *= al1;
        }

        CP_WAIT1();              // V[ci] ready (pending: K[ci+1] group)
        __syncthreads();         // barrier B

        // ---- O += P @ V (two 32-key halves) ----
        #pragma unroll
        for (int kp = 0; kp < 2; kp++){
            uint32_t pah[2][4], pal[2][4];
            #pragma unroll
            for (int kk = 0; kk < 2; kk++){
                int n0 = (kp*2 + kk)*2, n1 = n0 + 1;
                pah[kk][0] = packbf(sacc[n0][0], sacc[n0][1]);
                pah[kk][1] = packbf(sacc[n0][2], sacc[n0][3]);
                pah[kk][2] = packbf(sacc[n1][0], sacc[n1][1]);
                pah[kk][3] = packbf(sacc[n1][2], sacc[n1][3]);
                pal[kk][0] = packbf(resid(sacc[n0][0]), resid(sacc[n0][1]));
                pal[kk][1] = packbf(resid(sacc[n0][2]), resid(sacc[n0][3]));
                pal[kk][2] = packbf(resid(sacc[n1][0]), resid(sacc[n1][1]));
                pal[kk][3] = packbf(resid(sacc[n1][2]), resid(sacc[n1][3]));
            }
            uint32_t vrow = (uint32_t)kp*32 + lane;
            uint32_t vmask = (vrow & 7) << 4;
            uint32_t vbh = sb + 32768 + vrow*128;
            uint32_t vbl = sb + 40960 + vrow*128;
            #pragma unroll
            for (int nd = 0; nd < 8; nd++){
                uint32_t bvh[4], bvl[4];
                uint32_t off = ((uint32_t)nd*16) ^ vmask;
                ldsm4t(bvh, vbh + off);
                ldsm4t(bvl, vbl + off);
                mma16816(oacc[nd], pah[0], bvh+0);
                mma16816(oacc[nd], pah[0], bvl+0);
                mma16816(oacc[nd], pal[0], bvh+0);
                mma16816(oacc[nd], pah[1], bvh+2);
                mma16816(oacc[nd], pah[1], bvl+2);
                mma16816(oacc[nd], pal[1], bvh+2);
            }
        }
    }
    CP_WAIT0();
    __syncthreads();

    // ---- epilogue: normalize, two 64-row passes, split concat writes ----
    float inv0 = 1.f / l0, inv1 = 1.f / l1;
    float* smf = (float*)sm;
    #pragma unroll
    for (int hf = 0; hf < 2; hf++){
        if ((wid >> 2) == hf){
            int r0l = (wid & 3)*16 + (lane >> 2), r1l = r0l + 8;
            #pragma unroll
            for (int nd = 0; nd < 8; nd++){
                int cb = nd*8 + 2*(lane & 3);
                smf[r0l*68 + cb]   = oacc[nd][0]*inv0;
                smf[r0l*68 + cb+1] = oacc[nd][1]*inv0;
                smf[r1l*68 + cb]   = oacc[nd][2]*inv1;
                smf[r1l*68 + cb+1] = oacc[nd][3]*inv1;
            }
        }
        __syncthreads();
        #pragma unroll
        for (int it = 0; it < 8; it++){
            int id = tid + it*256;
            int r = id >> 5, c2 = (id & 31)*2;
            int gr = row0 + hf*64 + r;
            float x = smf[r*68 + c2], y = smf[r*68 + c2 + 1];
            size_t g = ((size_t)(b*Sx + gr))*Dx + h*DKx + c2;
            __nv_bfloat162 th, tl;
            th.x = __float2bfloat16(x); th.y = __float2bfloat16(y);
            tl.x = __float2bfloat16(x - __bfloat162float(th.x));
            tl.y = __float2bfloat16(y - __bfloat162float(th.y));
            *(__nv_bfloat162*)(g_aoh + g) = th;
            *(__nv_bfloat162*)(g_aol + g) = tl;
        }
        __syncthreads();
    }
}

// --------------------------------- launch -----------------------------------
extern "C" void kernel_launch(void* const* d_in, const int* in_sizes, int n_in,
                              void* d_out, int out_size)
{
    const float* bq = (const float*)d_in[4];
    const float* bk = (const float*)d_in[6];
    const float* bv = (const float*)d_in[8];
    const float* bo = (const float*)d_in[10];
    float* out = (float*)d_out;

    split_all<<<dim3(Mx*Dx/4/256, 7), 256>>>(
        (const float4*)d_in[0], (const float4*)d_in[1], (const float4*)d_in[2],
        (const float4*)d_in[3], (const float4*)d_in[5], (const float4*)d_in[7],
        (const float4*)d_in[9]);

    // all three projections in one launch (z = q/k/v)
    gemm_hmma<1><<<dim3(Mx/64, Dx/64, 3), 128>>>(bq, bk, bv, nullptr);

    flash_kernel<<<dim3(Sx/128, BHx), 256>>>();

    gemm_hmma<0><<<dim3(Mx/64, Dx/64, 1), 128>>>(bo, bo, bo, out);
}